// round 11
// baseline (speedup 1.0000x reference)
#include <cuda_runtime.h>
#include <math.h>
#include <stdint.h>

#define BB      4
#define NSEQ    512
#define DMODEL  512
#define NH      8
#define DK      64
#define TOK     (BB*NSEQ)      // 2048
#define DINNER  2048
#define LN_EPS  1e-6f
#define INV_T   0.125f         // 1/sqrt(64)

// ---------------- scratch ----------------------------------------------------
__device__ float g_q[BB*NH*NSEQ*DK];        // [b,h,n,d]
__device__ float g_k[BB*NH*NSEQ*DK];        // [b,h,n,d]
__device__ float g_v[BB*NH*NSEQ*DK];        // [b,h,n,d]
__device__ float g_Mmat[DK*4];              // combined rp matrix  M[d][p]
__device__ float g_cvec[DK];                // combined rp bias    c[d]
__device__ float g_heads[TOK*DMODEL];       // [b,n, h*dv]
__device__ float g_tmp1[TOK*DMODEL];
__device__ float g_ln1[TOK*DMODEL];
__device__ float g_ffh[TOK*DINNER];
__device__ float g_tmp2[TOK*DMODEL];

// ---------------- helpers ----------------------------------------------------
__device__ __forceinline__ float warp_sum(float v) {
    #pragma unroll
    for (int o = 16; o; o >>= 1) v += __shfl_xor_sync(0xffffffffu, v, o);
    return v;
}
__device__ __forceinline__ float warp_max(float v) {
    #pragma unroll
    for (int o = 16; o; o >>= 1) v = fmaxf(v, __shfl_xor_sync(0xffffffffu, v, o));
    return v;
}
__device__ __forceinline__ float to_tf32(float x) {
    uint32_t u;
    asm("cvt.rna.tf32.f32 %0, %1;" : "=r"(u) : "f"(x));
    return __uint_as_float(u);
}
__device__ __forceinline__ void mma_tf32(float (&c)[4], const uint32_t (&a)[4],
                                         const uint32_t (&b)[2]) {
    asm volatile(
        "mma.sync.aligned.m16n8k8.row.col.f32.tf32.tf32.f32 "
        "{%0,%1,%2,%3}, {%4,%5,%6,%7}, {%8,%9}, {%0,%1,%2,%3};\n"
        : "+f"(c[0]), "+f"(c[1]), "+f"(c[2]), "+f"(c[3])
        : "r"(a[0]), "r"(a[1]), "r"(a[2]), "r"(a[3]), "r"(b[0]), "r"(b[1]));
}

// ---------------- collapse rel-pos MLP: M = W2@W1, c = W2@b1 + b2 -----------
__global__ void rp_combine_kernel(const float* __restrict__ w1, const float* __restrict__ b1,
                                  const float* __restrict__ w2, const float* __restrict__ b2) {
    int d = threadIdx.x;
    if (d >= DK) return;
    float m0 = 0.f, m1 = 0.f, m2 = 0.f, m3 = 0.f, cc = 0.f;
    for (int k = 0; k < DK; k++) {
        float w = w2[d*DK + k];
        m0 = fmaf(w, w1[k*4+0], m0);
        m1 = fmaf(w, w1[k*4+1], m1);
        m2 = fmaf(w, w1[k*4+2], m2);
        m3 = fmaf(w, w1[k*4+3], m3);
        cc = fmaf(w, b1[k],      cc);
    }
    g_Mmat[d*4+0] = m0; g_Mmat[d*4+1] = m1;
    g_Mmat[d*4+2] = m2; g_Mmat[d*4+3] = m3;
    g_cvec[d] = cc + b2[d];
}

// ============================================================================
// QKV projection via 3xTF32 split MMA (fp32-grade accuracy on tensor cores).
// ============================================================================
__global__ __launch_bounds__(256)
void qkv3_kernel(const float* __restrict__ A,
                 const float* __restrict__ B0, const float* __restrict__ B1,
                 const float* __restrict__ B2, int colbase)
{
    const int K = DMODEL;
    __shared__ __align__(16) float Ah[2][8][136], Al[2][8][136];
    __shared__ __align__(16) float Bh[2][8][136], Bl[2][8][136];

    int tid  = threadIdx.x;
    int lane = tid & 31, warp = tid >> 5;
    int wm = warp >> 2, wn = warp & 3;
    int qr = lane >> 2, qc = lane & 3;
    int row0 = blockIdx.y << 7;
    int col0 = colbase + (blockIdx.x << 7);

    int wsel = col0 >> 9;
    const float* Bw = (wsel == 0) ? B0 : ((wsel == 1) ? B1 : B2);
    const float* Bb = Bw + (size_t)(col0 & 511) * K;

    int ar = tid >> 1, ak4 = (tid & 1) << 2;
    const float* Ald = A + (size_t)(row0 + ar) * K + ak4;
    const float* Bld = Bb + (size_t)ar * K + ak4;

    float acc[4][4][4];
    #pragma unroll
    for (int mt = 0; mt < 4; mt++)
        #pragma unroll
        for (int nt = 0; nt < 4; nt++)
            #pragma unroll
            for (int c = 0; c < 4; c++) acc[mt][nt][c] = 0.f;

    float4 av, bv;
    auto ldG = [&](int k0) {
        av = *(const float4*)(Ald + k0);
        bv = *(const float4*)(Bld + k0);
    };
    auto stS = [&](int buf) {
        const float* ap = (const float*)&av;
        const float* bp = (const float*)&bv;
        #pragma unroll
        for (int e = 0; e < 4; e++) {
            float x = ap[e], h = to_tf32(x);
            Ah[buf][ak4+e][ar] = h;
            Al[buf][ak4+e][ar] = to_tf32(x - h);
            float y = bp[e], g = to_tf32(y);
            Bh[buf][ak4+e][ar] = g;
            Bl[buf][ak4+e][ar] = to_tf32(y - g);
        }
    };
    auto compute = [&](int buf) {
        uint32_t afh[4][4], afl[4][4], bfh[4][2], bfl[4][2];
        #pragma unroll
        for (int mt = 0; mt < 4; mt++) {
            int mb = wm * 64 + mt * 16;
            afh[mt][0] = __float_as_uint(Ah[buf][qc  ][mb+qr  ]);
            afh[mt][1] = __float_as_uint(Ah[buf][qc  ][mb+qr+8]);
            afh[mt][2] = __float_as_uint(Ah[buf][qc+4][mb+qr  ]);
            afh[mt][3] = __float_as_uint(Ah[buf][qc+4][mb+qr+8]);
            afl[mt][0] = __float_as_uint(Al[buf][qc  ][mb+qr  ]);
            afl[mt][1] = __float_as_uint(Al[buf][qc  ][mb+qr+8]);
            afl[mt][2] = __float_as_uint(Al[buf][qc+4][mb+qr  ]);
            afl[mt][3] = __float_as_uint(Al[buf][qc+4][mb+qr+8]);
        }
        #pragma unroll
        for (int nt = 0; nt < 4; nt++) {
            int nb = wn * 32 + nt * 8;
            bfh[nt][0] = __float_as_uint(Bh[buf][qc  ][nb+qr]);
            bfh[nt][1] = __float_as_uint(Bh[buf][qc+4][nb+qr]);
            bfl[nt][0] = __float_as_uint(Bl[buf][qc  ][nb+qr]);
            bfl[nt][1] = __float_as_uint(Bl[buf][qc+4][nb+qr]);
        }
        #pragma unroll
        for (int mt = 0; mt < 4; mt++)
            #pragma unroll
            for (int nt = 0; nt < 4; nt++) {
                mma_tf32(acc[mt][nt], afh[mt], bfh[nt]);
                mma_tf32(acc[mt][nt], afh[mt], bfl[nt]);
                mma_tf32(acc[mt][nt], afl[mt], bfh[nt]);
            }
    };

    ldG(0);
    stS(0);
    __syncthreads();
    int buf = 0;
    for (int k0 = 8; k0 < K; k0 += 8) {
        ldG(k0);
        compute(buf);
        stS(buf ^ 1);
        __syncthreads();
        buf ^= 1;
    }
    compute(buf);

    #pragma unroll
    for (int mt = 0; mt < 4; mt++) {
        int rbase = row0 + wm * 64 + mt * 16 + qr;
        #pragma unroll
        for (int nt = 0; nt < 4; nt++) {
            int c = col0 + wn * 32 + nt * 8 + 2 * qc;
            int ws = c >> 9, cc = c & 511;
            int h = cc >> 6, d = cc & 63;
            float* dst = (ws == 0) ? g_q : ((ws == 1) ? g_k : g_v);
            #pragma unroll
            for (int hh = 0; hh < 2; hh++) {
                int r = rbase + hh * 8;
                int b = r >> 9, n = r & 511;
                float2 v = make_float2(acc[mt][nt][2*hh], acc[mt][nt][2*hh+1]);
                *(float2*)(dst + ((((size_t)b * NH + h) * NSEQ) + n) * DK + d) = v;
            }
        }
    }
}

// ============================================================================
// TF32 tensor-core GEMM (AV, fc, FFN1, FFN2)
// ============================================================================
template<int TN, int MAP, bool BTRANS, bool BIAS, bool RELU, bool RESID>
__global__ __launch_bounds__(256)
void tgemm_kernel(const float* __restrict__ A, const float* __restrict__ B0,
                  const float* __restrict__ bias, const float* __restrict__ resid,
                  float* __restrict__ C, int N, int K,
                  size_t strideA, size_t strideB)
{
    constexpr int NT   = TN / 32;
    constexpr int WN   = TN / 4;
    constexpr int BPAD = (TN == 128) ? 136 : 72;

    __shared__ __align__(16) float As[2][16][136];
    __shared__ __align__(16) float Bs[2][16][BPAD];

    int tid  = threadIdx.x;
    int lane = tid & 31, warp = tid >> 5;
    int wm = warp >> 2, wn = warp & 3;
    int qr = lane >> 2, qc = lane & 3;
    int row0 = blockIdx.y << 7;
    int col0 = blockIdx.x * TN;
    int z    = blockIdx.z;

    const float* Ab = A + (size_t)z * strideA;
    const float* Bb = BTRANS ? (B0 + (size_t)col0 * K)
                             : (B0 + (size_t)z * strideB + col0);

    int ar = tid >> 2, ak = (tid & 3) << 2;
    const float* Ald = Ab + (size_t)(row0 + ar) * K + ak;
    const float* Bld_t = Bb + (size_t)ar * K + ak;
    int bkr = tid >> 4, bn4 = (tid & 15) << 2;
    const float* Bld_n = Bb + (size_t)bkr * N + bn4;

    float acc[4][NT][4];
    #pragma unroll
    for (int mt = 0; mt < 4; mt++)
        #pragma unroll
        for (int nt = 0; nt < NT; nt++)
            #pragma unroll
            for (int c = 0; c < 4; c++) acc[mt][nt][c] = 0.f;

    float4 av[2], bv[2];
    auto ldG = [&](int k0) {
        av[0] = *(const float4*)(Ald + k0);
        av[1] = *(const float4*)(Ald + (size_t)64 * K + k0);
        if (BTRANS) {
            bv[0] = *(const float4*)(Bld_t + k0);
            if (TN == 128) bv[1] = *(const float4*)(Bld_t + (size_t)64 * K + k0);
        } else {
            bv[0] = *(const float4*)(Bld_n + (size_t)k0 * N);
        }
    };
    auto stS = [&](int buf) {
        #pragma unroll
        for (int h = 0; h < 2; h++) {
            int r = ar + h * 64;
            As[buf][ak+0][r] = to_tf32(((const float*)&av[h])[0]);
            As[buf][ak+1][r] = to_tf32(((const float*)&av[h])[1]);
            As[buf][ak+2][r] = to_tf32(((const float*)&av[h])[2]);
            As[buf][ak+3][r] = to_tf32(((const float*)&av[h])[3]);
        }
        if (BTRANS) {
            #pragma unroll
            for (int h = 0; h < (TN == 128 ? 2 : 1); h++) {
                int r = ar + h * 64;
                if (TN == 128 || r < TN) {
                    Bs[buf][ak+0][r] = to_tf32(((const float*)&bv[h])[0]);
                    Bs[buf][ak+1][r] = to_tf32(((const float*)&bv[h])[1]);
                    Bs[buf][ak+2][r] = to_tf32(((const float*)&bv[h])[2]);
                    Bs[buf][ak+3][r] = to_tf32(((const float*)&bv[h])[3]);
                }
            }
        } else {
            float4 t = make_float4(to_tf32(bv[0].x), to_tf32(bv[0].y),
                                   to_tf32(bv[0].z), to_tf32(bv[0].w));
            *(float4*)&Bs[buf][bkr][bn4] = t;
        }
    };
    auto compute = [&](int buf) {
        #pragma unroll
        for (int ks = 0; ks < 2; ks++) {
            int kb = ks * 8;
            uint32_t af[4][4], bf[NT][2];
            #pragma unroll
            for (int mt = 0; mt < 4; mt++) {
                int mb = wm * 64 + mt * 16;
                af[mt][0] = __float_as_uint(As[buf][kb+qc  ][mb+qr  ]);
                af[mt][1] = __float_as_uint(As[buf][kb+qc  ][mb+qr+8]);
                af[mt][2] = __float_as_uint(As[buf][kb+qc+4][mb+qr  ]);
                af[mt][3] = __float_as_uint(As[buf][kb+qc+4][mb+qr+8]);
            }
            #pragma unroll
            for (int nt = 0; nt < NT; nt++) {
                int nb = wn * WN + nt * 8;
                bf[nt][0] = __float_as_uint(Bs[buf][kb+qc  ][nb+qr]);
                bf[nt][1] = __float_as_uint(Bs[buf][kb+qc+4][nb+qr]);
            }
            #pragma unroll
            for (int mt = 0; mt < 4; mt++)
                #pragma unroll
                for (int nt = 0; nt < NT; nt++)
                    mma_tf32(acc[mt][nt], af[mt], bf[nt]);
        }
    };

    ldG(0);
    stS(0);
    __syncthreads();
    int buf = 0;
    for (int k0 = 16; k0 < K; k0 += 16) {
        ldG(k0);
        compute(buf);
        stS(buf ^ 1);
        __syncthreads();
        buf ^= 1;
    }
    compute(buf);

    #pragma unroll
    for (int mt = 0; mt < 4; mt++) {
        int rbase = row0 + wm * 64 + mt * 16 + qr;
        #pragma unroll
        for (int nt = 0; nt < NT; nt++) {
            int cg = col0 + wn * WN + nt * 8 + 2 * qc;
            #pragma unroll
            for (int hh = 0; hh < 2; hh++) {
                int r = rbase + hh * 8;
                float2 v = make_float2(acc[mt][nt][2*hh], acc[mt][nt][2*hh+1]);
                if (BIAS) { v.x += bias[cg]; v.y += bias[cg+1]; }
                if (RESID) {
                    const float2 rz = *(const float2*)(resid + (size_t)r * N + cg);
                    v.x += rz.x; v.y += rz.y;
                }
                if (RELU) { v.x = fmaxf(v.x, 0.f); v.y = fmaxf(v.y, 0.f); }
                if (MAP == 0) {
                    *(float2*)(C + (size_t)r * N + cg) = v;
                } else {
                    int b = z >> 3, h2 = z & 7;
                    *(float2*)(g_heads + ((size_t)(b * NSEQ) + r) * DMODEL + h2 * DK + cg) = v;
                }
            }
        }
    }
}

// ============================================================================
// scores v3: tensor-core 5-channel decomposition, compensated tf32 split.
// attn[b,h,j,i] = (1/T)*( S_c + sum_p pos[b,j,i,p]*S_p ),  S_x = K @ (q.*w_x)^T
// Block = 64j x 64i tile of one (b,h); 8 warps (wm 0..1 x wn 0..3).
// Smem planes hold PRE-SWIZZLED mma fragments:
//   A (K) hi/lo planes: float4 per lane = {(dlo,j),(dlo,j+8),(dhi,j),(dhi,j+8)}
//   B (Q'ch) planes:    float4 per lane = {hi(dlo),hi(dhi),lo(dlo),lo(dhi)}
// Row stride 132 floats (128 data + 4 pad) -> conflict-free LDS.128.
// ============================================================================
#define SC_AH 0
#define SC_AL 4224
#define SC_B  8448          /* 5 planes x 8448 floats */
#define SC_W  50688         /* 5 x 64 weights */
#define SC_SMEM_BYTES (51008*4)

__global__ __launch_bounds__(256)
void scores_tc_kernel(const float* __restrict__ pos, float* __restrict__ attn)
{
    extern __shared__ float sm[];
    int tid  = threadIdx.x;
    int lane = tid & 31, warp = tid >> 5;
    int wm = warp >> 2, wn = warp & 3;
    int qr = lane >> 2, qc = lane & 3;
    int i0 = blockIdx.x << 6, j0 = blockIdx.y << 6;
    int z  = blockIdx.z;                 // b*NH + h
    int bb = z >> 3;

    // channel weights: w_p[d] = M[d][p] (p<4), w_4[d] = c[d]
    if (tid < DK) {
        #pragma unroll
        for (int p = 0; p < 4; p++) sm[SC_W + p*64 + tid] = g_Mmat[tid*4+p];
        sm[SC_W + 4*64 + tid] = g_cvec[tid];
    }

    // ---- build A (K tile, hi/lo, swizzled) ----
    {
        int rp = tid >> 3, ksw = tid & 7;
        int g = rp >> 3, qrw = rp & 7;
        int j = g*16 + qrw;
        const float* kp = g_k + ((size_t)z*NSEQ + j0 + j)*DK + ksw*8;
        float4 a0 = *(const float4*)(kp);
        float4 a1 = *(const float4*)(kp + 4);
        float4 b0 = *(const float4*)(kp + 8*DK);
        float4 b1 = *(const float4*)(kp + 8*DK + 4);
        const float* a0p = (const float*)&a0; const float* a1p = (const float*)&a1;
        const float* b0p = (const float*)&b0; const float* b1p = (const float*)&b1;
        int rowaddr = (g*8 + ksw)*132 + qrw*16;
        #pragma unroll
        for (int e = 0; e < 4; e++) {
            float v0 = a0p[e], v1 = b0p[e], v2 = a1p[e], v3 = b1p[e];
            float h0 = to_tf32(v0), h1 = to_tf32(v1), h2 = to_tf32(v2), h3 = to_tf32(v3);
            *(float4*)&sm[SC_AH + rowaddr + e*4] = make_float4(h0, h1, h2, h3);
            *(float4*)&sm[SC_AL + rowaddr + e*4] =
                make_float4(to_tf32(v0-h0), to_tf32(v1-h1), to_tf32(v2-h2), to_tf32(v3-h3));
        }
    }
    __syncthreads();   // W ready for Q' build

    // ---- build B (Q' channels, hi/lo interleaved, swizzled) ----
    {
        int ksw = tid & 7, nloc = tid >> 3;
        #pragma unroll
        for (int pass = 0; pass < 2; pass++) {
            int n = nloc + 32*pass;
            const float* qp = g_q + ((size_t)z*NSEQ + i0 + n)*DK + ksw*8;
            float4 q0 = *(const float4*)(qp);
            float4 q1 = *(const float4*)(qp + 4);
            const float* q0p = (const float*)&q0; const float* q1p = (const float*)&q1;
            int rowaddr = ((n>>3)*8 + ksw)*132 + (n&7)*16;
            #pragma unroll
            for (int ch = 0; ch < 5; ch++) {
                const float* w = &sm[SC_W + ch*64 + ksw*8];
                int baddr = SC_B + ch*8448 + rowaddr;
                #pragma unroll
                for (int e = 0; e < 4; e++) {
                    float p0 = q0p[e]*w[e];
                    float p1 = q1p[e]*w[e+4];
                    float h0 = to_tf32(p0), h1 = to_tf32(p1);
                    *(float4*)&sm[baddr + e*4] =
                        make_float4(h0, h1, to_tf32(p0-h0), to_tf32(p1-h1));
                }
            }
        }
    }
    __syncthreads();

    // ---- mma mainloop: 8 ksteps over d ----
    float acc[5][2][2][4];
    #pragma unroll
    for (int ch = 0; ch < 5; ch++)
        #pragma unroll
        for (int mt = 0; mt < 2; mt++)
            #pragma unroll
            for (int nt = 0; nt < 2; nt++)
                #pragma unroll
                for (int c = 0; c < 4; c++) acc[ch][mt][nt][c] = 0.f;

    #pragma unroll
    for (int ks = 0; ks < 8; ks++) {
        uint32_t ah[2][4], al[2][4];
        #pragma unroll
        for (int mt = 0; mt < 2; mt++) {
            int mg = wm*2 + mt;
            float4 h = *(const float4*)&sm[SC_AH + (mg*8+ks)*132 + lane*4];
            float4 l = *(const float4*)&sm[SC_AL + (mg*8+ks)*132 + lane*4];
            ah[mt][0] = __float_as_uint(h.x); ah[mt][1] = __float_as_uint(h.y);
            ah[mt][2] = __float_as_uint(h.z); ah[mt][3] = __float_as_uint(h.w);
            al[mt][0] = __float_as_uint(l.x); al[mt][1] = __float_as_uint(l.y);
            al[mt][2] = __float_as_uint(l.z); al[mt][3] = __float_as_uint(l.w);
        }
        #pragma unroll
        for (int ch = 0; ch < 5; ch++)
            #pragma unroll
            for (int nt = 0; nt < 2; nt++) {
                int ng = wn*2 + nt;
                float4 bq = *(const float4*)&sm[SC_B + ch*8448 + (ng*8+ks)*132 + lane*4];
                uint32_t bh[2] = {__float_as_uint(bq.x), __float_as_uint(bq.y)};
                uint32_t bl[2] = {__float_as_uint(bq.z), __float_as_uint(bq.w)};
                #pragma unroll
                for (int mt = 0; mt < 2; mt++) {
                    mma_tf32(acc[ch][mt][nt], ah[mt], bh);
                    mma_tf32(acc[ch][mt][nt], ah[mt], bl);
                    mma_tf32(acc[ch][mt][nt], al[mt], bh);
                }
            }
    }

    // ---- epilogue: combine 5 channels with pos, scale, store ----
    #pragma unroll
    for (int mt = 0; mt < 2; mt++)
        #pragma unroll
        for (int nt = 0; nt < 2; nt++) {
            int colb = i0 + wn*16 + nt*8 + 2*qc;
            #pragma unroll
            for (int hf = 0; hf < 2; hf++) {
                int row = j0 + wm*32 + mt*16 + qr + 8*hf;
                const float* pp = pos + (((size_t)(bb*NSEQ + row))*NSEQ + colb)*4;
                float4 p0 = *(const float4*)pp;
                float4 p1 = *(const float4*)(pp + 4);
                int c = 2*hf;
                float s0 = acc[4][mt][nt][c]
                         + p0.x*acc[0][mt][nt][c] + p0.y*acc[1][mt][nt][c]
                         + p0.z*acc[2][mt][nt][c] + p0.w*acc[3][mt][nt][c];
                float s1 = acc[4][mt][nt][c+1]
                         + p1.x*acc[0][mt][nt][c+1] + p1.y*acc[1][mt][nt][c+1]
                         + p1.z*acc[2][mt][nt][c+1] + p1.w*acc[3][mt][nt][c+1];
                *(float2*)(attn + ((size_t)z*NSEQ + row)*NSEQ + colb) =
                    make_float2(s0*INV_T, s1*INV_T);
            }
        }
}

// ---------------- softmax over last axis, in place ---------------------------
__global__ __launch_bounds__(256)
void softmax_kernel(float* __restrict__ attn)
{
    size_t row = blockIdx.x;
    float* p = attn + row * NSEQ;
    int tid = threadIdx.x;
    __shared__ float redm[8];
    __shared__ float reds[8];

    float v0 = p[tid], v1 = p[tid + 256];
    float m = warp_max(fmaxf(v0, v1));
    if ((tid & 31) == 0) redm[tid >> 5] = m;
    __syncthreads();
    m = redm[0];
    #pragma unroll
    for (int w = 1; w < 8; w++) m = fmaxf(m, redm[w]);

    float e0 = __expf(v0 - m), e1 = __expf(v1 - m);
    float s = warp_sum(e0 + e1);
    if ((tid & 31) == 0) reds[tid >> 5] = s;
    __syncthreads();
    s = reds[0];
    #pragma unroll
    for (int w = 1; w < 8; w++) s += reds[w];

    float inv = 1.0f / s;
    p[tid]       = e0 * inv;
    p[tid + 256] = e1 * inv;
}

// ---------------- layer norm (one token per block) ---------------------------
__global__ __launch_bounds__(256)
void layernorm_kernel(const float* __restrict__ x, const float* __restrict__ gam,
                      const float* __restrict__ bet, float* __restrict__ out)
{
    int t = blockIdx.x, tid = threadIdx.x;
    const float* xr = x + (size_t)t * DMODEL;
    __shared__ float red[8];

    float a0 = xr[tid], a1 = xr[tid + 256];
    float s = warp_sum(a0 + a1);
    if ((tid & 31) == 0) red[tid >> 5] = s;
    __syncthreads();
    s = red[0];
    #pragma unroll
    for (int w = 1; w < 8; w++) s += red[w];
    float mu = s * (1.0f / DMODEL);
    float d0 = a0 - mu, d1 = a1 - mu;
    __syncthreads();

    float q = warp_sum(d0*d0 + d1*d1);
    if ((tid & 31) == 0) red[tid >> 5] = q;
    __syncthreads();
    q = red[0];
    #pragma unroll
    for (int w = 1; w < 8; w++) q += red[w];
    float inv = rsqrtf(q * (1.0f / DMODEL) + LN_EPS);

    float* orow = out + (size_t)t * DMODEL;
    orow[tid]       = d0 * inv * gam[tid]       + bet[tid];
    orow[tid + 256] = d1 * inv * gam[tid + 256] + bet[tid + 256];
}

// ---------------- launch -----------------------------------------------------
extern "C" void kernel_launch(void* const* d_in, const int* in_sizes, int n_in,
                              void* d_out, int out_size)
{
    (void)in_sizes; (void)n_in; (void)out_size;
    const float* enc    = (const float*)d_in[0];
    const float* pos    = (const float*)d_in[1];
    const float* w_qs   = (const float*)d_in[2];
    const float* w_ks   = (const float*)d_in[3];
    const float* w_vs   = (const float*)d_in[4];
    const float* w_fc   = (const float*)d_in[5];
    const float* rp_w1  = (const float*)d_in[6];
    const float* rp_b1  = (const float*)d_in[7];
    const float* rp_w2  = (const float*)d_in[8];
    const float* rp_b2  = (const float*)d_in[9];
    const float* ln1_g  = (const float*)d_in[10];
    const float* ln1_b  = (const float*)d_in[11];
    const float* ln2_g  = (const float*)d_in[12];
    const float* ln2_b  = (const float*)d_in[13];
    const float* ffn_w1 = (const float*)d_in[14];
    const float* ffn_b1 = (const float*)d_in[15];
    const float* ffn_w2 = (const float*)d_in[16];
    const float* ffn_b2 = (const float*)d_in[17];

    float* out2 = (float*)d_out;                          // [4,512,512]
    float* attn = out2 + (size_t)TOK * DMODEL;            // [4,8,512,512]

    float *pv, *pheads, *ptmp1, *pln1, *pffh, *ptmp2;
    cudaGetSymbolAddress((void**)&pv,     g_v);
    cudaGetSymbolAddress((void**)&pheads, g_heads);
    cudaGetSymbolAddress((void**)&ptmp1,  g_tmp1);
    cudaGetSymbolAddress((void**)&pln1,   g_ln1);
    cudaGetSymbolAddress((void**)&pffh,   g_ffh);
    cudaGetSymbolAddress((void**)&ptmp2,  g_tmp2);

    // opt-in to 204 KB dynamic smem for the scores kernel (idempotent)
    cudaFuncSetAttribute(scores_tc_kernel,
                         cudaFuncAttributeMaxDynamicSharedMemorySize, SC_SMEM_BYTES);

    // 1) collapse rel-pos MLP
    rp_combine_kernel<<<1, 64>>>(rp_w1, rp_b1, rp_w2, rp_b2);

    // 2+3) QKV projection, 3xTF32 split, two column halves
    {
        dim3 g(6, TOK/128, 1);
        qkv3_kernel<<<g, 256>>>(enc, w_qs, w_ks, w_vs, 0);
        qkv3_kernel<<<g, 256>>>(enc, w_qs, w_ks, w_vs, 768);
    }

    // 4) relative-position attention logits on tensor cores
    {
        dim3 g(NSEQ/64, NSEQ/64, BB*NH);   // (8, 8, 32)
        scores_tc_kernel<<<g, 256, SC_SMEM_BYTES>>>(pos, attn);
    }

    // 5) softmax in place
    softmax_kernel<<<BB*NH*NSEQ, 256>>>(attn);

    // 6) AV (tf32): per (b,h): P[512,512] @ V[512,64] -> g_heads
    {
        dim3 g(1, NSEQ/128, BB*NH);
        tgemm_kernel<64, 2, false, false, false, false><<<g, 256>>>(
            attn, pv, nullptr, nullptr, nullptr,
            DK, NSEQ, (size_t)NSEQ*NSEQ, (size_t)NSEQ*DK);
    }

    // 7) fc + residual(enc) -> g_tmp1 (tf32); LN1
    {
        dim3 g(DMODEL/64, TOK/128, 1);
        tgemm_kernel<64, 0, true, false, false, true><<<g, 256>>>(
            pheads, w_fc, nullptr, enc, ptmp1, DMODEL, DMODEL, 0, 0);
    }
    layernorm_kernel<<<TOK, 256>>>(ptmp1, ln1_g, ln1_b, pln1);

    // 8) FFN1 (tf32): relu(ln1 @ W1^T + b1) -> g_ffh
    {
        dim3 g(DINNER/128, TOK/128, 1);
        tgemm_kernel<128, 0, true, true, true, false><<<g, 256>>>(
            pln1, ffn_w1, ffn_b1, nullptr, pffh, DINNER, DMODEL, 0, 0);
    }

    // 9) FFN2 (tf32): ffh @ W2^T + b2 + ln1 -> g_tmp2
    {
        dim3 g(DMODEL/64, TOK/128, 1);
        tgemm_kernel<64, 0, true, true, false, true><<<g, 256>>>(
            pffh, ffn_w2, ffn_b2, pln1, ptmp2, DMODEL, DINNER, 0, 0);
    }

    // 10) LN2 -> out2
    layernorm_kernel<<<TOK, 256>>>(ptmp2, ln2_g, ln2_b, out2);
}

// round 12
// speedup vs baseline: 1.0871x; 1.0871x over previous
#include <cuda_runtime.h>
#include <cuda_bf16.h>
#include <math.h>
#include <stdint.h>

#define BB      4
#define NSEQ    512
#define DMODEL  512
#define NH      8
#define DK      64
#define TOK     (BB*NSEQ)      // 2048
#define DINNER  2048
#define LN_EPS  1e-6f
#define INV_T   0.125f         // 1/sqrt(64)

// ---------------- scratch ----------------------------------------------------
__device__ float g_q[BB*NH*NSEQ*DK];        // [b,h,n,d]
__device__ float g_k[BB*NH*NSEQ*DK];        // [b,h,n,d]
__device__ float g_v[BB*NH*NSEQ*DK];        // [b,h,n,d]
__device__ float g_Mmat[DK*4];              // combined rp matrix  M[d][p]
__device__ float g_cvec[DK];                // combined rp bias    c[d]
__device__ float g_heads[TOK*DMODEL];       // [b,n, h*dv]
__device__ float g_tmp1[TOK*DMODEL];
__device__ float g_ln1[TOK*DMODEL];
__device__ float g_ffh[TOK*DINNER];
__device__ float g_tmp2[TOK*DMODEL];

// ---------------- helpers ----------------------------------------------------
__device__ __forceinline__ float warp_sum(float v) {
    #pragma unroll
    for (int o = 16; o; o >>= 1) v += __shfl_xor_sync(0xffffffffu, v, o);
    return v;
}
__device__ __forceinline__ float warp_max(float v) {
    #pragma unroll
    for (int o = 16; o; o >>= 1) v = fmaxf(v, __shfl_xor_sync(0xffffffffu, v, o));
    return v;
}
__device__ __forceinline__ float to_tf32(float x) {
    uint32_t u;
    asm("cvt.rna.tf32.f32 %0, %1;" : "=r"(u) : "f"(x));
    return __uint_as_float(u);
}
__device__ __forceinline__ void mma_tf32(float (&c)[4], const uint32_t (&a)[4],
                                         const uint32_t (&b)[2]) {
    asm volatile(
        "mma.sync.aligned.m16n8k8.row.col.f32.tf32.tf32.f32 "
        "{%0,%1,%2,%3}, {%4,%5,%6,%7}, {%8,%9}, {%0,%1,%2,%3};\n"
        : "+f"(c[0]), "+f"(c[1]), "+f"(c[2]), "+f"(c[3])
        : "r"(a[0]), "r"(a[1]), "r"(a[2]), "r"(a[3]), "r"(b[0]), "r"(b[1]));
}
__device__ __forceinline__ void mma_bf16(float (&c)[4], const uint4& a,
                                         uint32_t b0, uint32_t b1) {
    asm volatile(
        "mma.sync.aligned.m16n8k16.row.col.f32.bf16.bf16.f32 "
        "{%0,%1,%2,%3}, {%4,%5,%6,%7}, {%8,%9}, {%0,%1,%2,%3};\n"
        : "+f"(c[0]), "+f"(c[1]), "+f"(c[2]), "+f"(c[3])
        : "r"(a.x), "r"(a.y), "r"(a.z), "r"(a.w), "r"(b0), "r"(b1));
}
__device__ __forceinline__ uint32_t pkbf2(float x0, float x1) {
    __nv_bfloat162 v = __floats2bfloat162_rn(x0, x1);
    return *reinterpret_cast<uint32_t*>(&v);
}
__device__ __forceinline__ float bfhi(float x) {
    return __bfloat162float(__float2bfloat16(x));
}

// ---------------- collapse rel-pos MLP: M = W2@W1, c = W2@b1 + b2 -----------
__global__ void rp_combine_kernel(const float* __restrict__ w1, const float* __restrict__ b1,
                                  const float* __restrict__ w2, const float* __restrict__ b2) {
    int d = threadIdx.x;
    if (d >= DK) return;
    float m0 = 0.f, m1 = 0.f, m2 = 0.f, m3 = 0.f, cc = 0.f;
    for (int k = 0; k < DK; k++) {
        float w = w2[d*DK + k];
        m0 = fmaf(w, w1[k*4+0], m0);
        m1 = fmaf(w, w1[k*4+1], m1);
        m2 = fmaf(w, w1[k*4+2], m2);
        m3 = fmaf(w, w1[k*4+3], m3);
        cc = fmaf(w, b1[k],      cc);
    }
    g_Mmat[d*4+0] = m0; g_Mmat[d*4+1] = m1;
    g_Mmat[d*4+2] = m2; g_Mmat[d*4+3] = m3;
    g_cvec[d] = cc + b2[d];
}

// ============================================================================
// QKV projection via 3xTF32 split MMA (fp32-grade accuracy on tensor cores).
// ============================================================================
__global__ __launch_bounds__(256)
void qkv3_kernel(const float* __restrict__ A,
                 const float* __restrict__ B0, const float* __restrict__ B1,
                 const float* __restrict__ B2, int colbase)
{
    const int K = DMODEL;
    __shared__ __align__(16) float Ah[2][8][136], Al[2][8][136];
    __shared__ __align__(16) float Bh[2][8][136], Bl[2][8][136];

    int tid  = threadIdx.x;
    int lane = tid & 31, warp = tid >> 5;
    int wm = warp >> 2, wn = warp & 3;
    int qr = lane >> 2, qc = lane & 3;
    int row0 = blockIdx.y << 7;
    int col0 = colbase + (blockIdx.x << 7);

    int wsel = col0 >> 9;
    const float* Bw = (wsel == 0) ? B0 : ((wsel == 1) ? B1 : B2);
    const float* Bb = Bw + (size_t)(col0 & 511) * K;

    int ar = tid >> 1, ak4 = (tid & 1) << 2;
    const float* Ald = A + (size_t)(row0 + ar) * K + ak4;
    const float* Bld = Bb + (size_t)ar * K + ak4;

    float acc[4][4][4];
    #pragma unroll
    for (int mt = 0; mt < 4; mt++)
        #pragma unroll
        for (int nt = 0; nt < 4; nt++)
            #pragma unroll
            for (int c = 0; c < 4; c++) acc[mt][nt][c] = 0.f;

    float4 av, bv;
    auto ldG = [&](int k0) {
        av = *(const float4*)(Ald + k0);
        bv = *(const float4*)(Bld + k0);
    };
    auto stS = [&](int buf) {
        const float* ap = (const float*)&av;
        const float* bp = (const float*)&bv;
        #pragma unroll
        for (int e = 0; e < 4; e++) {
            float x = ap[e], h = to_tf32(x);
            Ah[buf][ak4+e][ar] = h;
            Al[buf][ak4+e][ar] = to_tf32(x - h);
            float y = bp[e], g = to_tf32(y);
            Bh[buf][ak4+e][ar] = g;
            Bl[buf][ak4+e][ar] = to_tf32(y - g);
        }
    };
    auto compute = [&](int buf) {
        uint32_t afh[4][4], afl[4][4], bfh[4][2], bfl[4][2];
        #pragma unroll
        for (int mt = 0; mt < 4; mt++) {
            int mb = wm * 64 + mt * 16;
            afh[mt][0] = __float_as_uint(Ah[buf][qc  ][mb+qr  ]);
            afh[mt][1] = __float_as_uint(Ah[buf][qc  ][mb+qr+8]);
            afh[mt][2] = __float_as_uint(Ah[buf][qc+4][mb+qr  ]);
            afh[mt][3] = __float_as_uint(Ah[buf][qc+4][mb+qr+8]);
            afl[mt][0] = __float_as_uint(Al[buf][qc  ][mb+qr  ]);
            afl[mt][1] = __float_as_uint(Al[buf][qc  ][mb+qr+8]);
            afl[mt][2] = __float_as_uint(Al[buf][qc+4][mb+qr  ]);
            afl[mt][3] = __float_as_uint(Al[buf][qc+4][mb+qr+8]);
        }
        #pragma unroll
        for (int nt = 0; nt < 4; nt++) {
            int nb = wn * 32 + nt * 8;
            bfh[nt][0] = __float_as_uint(Bh[buf][qc  ][nb+qr]);
            bfh[nt][1] = __float_as_uint(Bh[buf][qc+4][nb+qr]);
            bfl[nt][0] = __float_as_uint(Bl[buf][qc  ][nb+qr]);
            bfl[nt][1] = __float_as_uint(Bl[buf][qc+4][nb+qr]);
        }
        #pragma unroll
        for (int mt = 0; mt < 4; mt++)
            #pragma unroll
            for (int nt = 0; nt < 4; nt++) {
                mma_tf32(acc[mt][nt], afh[mt], bfh[nt]);
                mma_tf32(acc[mt][nt], afh[mt], bfl[nt]);
                mma_tf32(acc[mt][nt], afl[mt], bfh[nt]);
            }
    };

    ldG(0);
    stS(0);
    __syncthreads();
    int buf = 0;
    for (int k0 = 8; k0 < K; k0 += 8) {
        ldG(k0);
        compute(buf);
        stS(buf ^ 1);
        __syncthreads();
        buf ^= 1;
    }
    compute(buf);

    #pragma unroll
    for (int mt = 0; mt < 4; mt++) {
        int rbase = row0 + wm * 64 + mt * 16 + qr;
        #pragma unroll
        for (int nt = 0; nt < 4; nt++) {
            int c = col0 + wn * 32 + nt * 8 + 2 * qc;
            int ws = c >> 9, cc = c & 511;
            int h = cc >> 6, d = cc & 63;
            float* dst = (ws == 0) ? g_q : ((ws == 1) ? g_k : g_v);
            #pragma unroll
            for (int hh = 0; hh < 2; hh++) {
                int r = rbase + hh * 8;
                int b = r >> 9, n = r & 511;
                float2 v = make_float2(acc[mt][nt][2*hh], acc[mt][nt][2*hh+1]);
                *(float2*)(dst + ((((size_t)b * NH + h) * NSEQ) + n) * DK + d) = v;
            }
        }
    }
}

// ============================================================================
// TF32 tensor-core GEMM (AV, fc, FFN1, FFN2)
// ============================================================================
template<int TN, int MAP, bool BTRANS, bool BIAS, bool RELU, bool RESID>
__global__ __launch_bounds__(256)
void tgemm_kernel(const float* __restrict__ A, const float* __restrict__ B0,
                  const float* __restrict__ bias, const float* __restrict__ resid,
                  float* __restrict__ C, int N, int K,
                  size_t strideA, size_t strideB)
{
    constexpr int NT   = TN / 32;
    constexpr int WN   = TN / 4;
    constexpr int BPAD = (TN == 128) ? 136 : 72;

    __shared__ __align__(16) float As[2][16][136];
    __shared__ __align__(16) float Bs[2][16][BPAD];

    int tid  = threadIdx.x;
    int lane = tid & 31, warp = tid >> 5;
    int wm = warp >> 2, wn = warp & 3;
    int qr = lane >> 2, qc = lane & 3;
    int row0 = blockIdx.y << 7;
    int col0 = blockIdx.x * TN;
    int z    = blockIdx.z;

    const float* Ab = A + (size_t)z * strideA;
    const float* Bb = BTRANS ? (B0 + (size_t)col0 * K)
                             : (B0 + (size_t)z * strideB + col0);

    int ar = tid >> 2, ak = (tid & 3) << 2;
    const float* Ald = Ab + (size_t)(row0 + ar) * K + ak;
    const float* Bld_t = Bb + (size_t)ar * K + ak;
    int bkr = tid >> 4, bn4 = (tid & 15) << 2;
    const float* Bld_n = Bb + (size_t)bkr * N + bn4;

    float acc[4][NT][4];
    #pragma unroll
    for (int mt = 0; mt < 4; mt++)
        #pragma unroll
        for (int nt = 0; nt < NT; nt++)
            #pragma unroll
            for (int c = 0; c < 4; c++) acc[mt][nt][c] = 0.f;

    float4 av[2], bv[2];
    auto ldG = [&](int k0) {
        av[0] = *(const float4*)(Ald + k0);
        av[1] = *(const float4*)(Ald + (size_t)64 * K + k0);
        if (BTRANS) {
            bv[0] = *(const float4*)(Bld_t + k0);
            if (TN == 128) bv[1] = *(const float4*)(Bld_t + (size_t)64 * K + k0);
        } else {
            bv[0] = *(const float4*)(Bld_n + (size_t)k0 * N);
        }
    };
    auto stS = [&](int buf) {
        #pragma unroll
        for (int h = 0; h < 2; h++) {
            int r = ar + h * 64;
            As[buf][ak+0][r] = to_tf32(((const float*)&av[h])[0]);
            As[buf][ak+1][r] = to_tf32(((const float*)&av[h])[1]);
            As[buf][ak+2][r] = to_tf32(((const float*)&av[h])[2]);
            As[buf][ak+3][r] = to_tf32(((const float*)&av[h])[3]);
        }
        if (BTRANS) {
            #pragma unroll
            for (int h = 0; h < (TN == 128 ? 2 : 1); h++) {
                int r = ar + h * 64;
                if (TN == 128 || r < TN) {
                    Bs[buf][ak+0][r] = to_tf32(((const float*)&bv[h])[0]);
                    Bs[buf][ak+1][r] = to_tf32(((const float*)&bv[h])[1]);
                    Bs[buf][ak+2][r] = to_tf32(((const float*)&bv[h])[2]);
                    Bs[buf][ak+3][r] = to_tf32(((const float*)&bv[h])[3]);
                }
            }
        } else {
            float4 t = make_float4(to_tf32(bv[0].x), to_tf32(bv[0].y),
                                   to_tf32(bv[0].z), to_tf32(bv[0].w));
            *(float4*)&Bs[buf][bkr][bn4] = t;
        }
    };
    auto compute = [&](int buf) {
        #pragma unroll
        for (int ks = 0; ks < 2; ks++) {
            int kb = ks * 8;
            uint32_t af[4][4], bf[NT][2];
            #pragma unroll
            for (int mt = 0; mt < 4; mt++) {
                int mb = wm * 64 + mt * 16;
                af[mt][0] = __float_as_uint(As[buf][kb+qc  ][mb+qr  ]);
                af[mt][1] = __float_as_uint(As[buf][kb+qc  ][mb+qr+8]);
                af[mt][2] = __float_as_uint(As[buf][kb+qc+4][mb+qr  ]);
                af[mt][3] = __float_as_uint(As[buf][kb+qc+4][mb+qr+8]);
            }
            #pragma unroll
            for (int nt = 0; nt < NT; nt++) {
                int nb = wn * WN + nt * 8;
                bf[nt][0] = __float_as_uint(Bs[buf][kb+qc  ][nb+qr]);
                bf[nt][1] = __float_as_uint(Bs[buf][kb+qc+4][nb+qr]);
            }
            #pragma unroll
            for (int mt = 0; mt < 4; mt++)
                #pragma unroll
                for (int nt = 0; nt < NT; nt++)
                    mma_tf32(acc[mt][nt], af[mt], bf[nt]);
        }
    };

    ldG(0);
    stS(0);
    __syncthreads();
    int buf = 0;
    for (int k0 = 16; k0 < K; k0 += 16) {
        ldG(k0);
        compute(buf);
        stS(buf ^ 1);
        __syncthreads();
        buf ^= 1;
    }
    compute(buf);

    #pragma unroll
    for (int mt = 0; mt < 4; mt++) {
        int rbase = row0 + wm * 64 + mt * 16 + qr;
        #pragma unroll
        for (int nt = 0; nt < NT; nt++) {
            int cg = col0 + wn * WN + nt * 8 + 2 * qc;
            #pragma unroll
            for (int hh = 0; hh < 2; hh++) {
                int r = rbase + hh * 8;
                float2 v = make_float2(acc[mt][nt][2*hh], acc[mt][nt][2*hh+1]);
                if (BIAS) { v.x += bias[cg]; v.y += bias[cg+1]; }
                if (RESID) {
                    const float2 rz = *(const float2*)(resid + (size_t)r * N + cg);
                    v.x += rz.x; v.y += rz.y;
                }
                if (RELU) { v.x = fmaxf(v.x, 0.f); v.y = fmaxf(v.y, 0.f); }
                if (MAP == 0) {
                    *(float2*)(C + (size_t)r * N + cg) = v;
                } else {
                    int b = z >> 3, h2 = z & 7;
                    *(float2*)(g_heads + ((size_t)(b * NSEQ) + r) * DMODEL + h2 * DK + cg) = v;
                }
            }
        }
    }
}

// ============================================================================
// scores v4: bf16 3-term compensated, m16n8k16, tile 64j x 32i, 2 CTAs/SM.
// attn[b,h,j,i] = (1/T)*( S_c + sum_p pos[b,j,i,p]*S_p ),  S_x = K @ (q.*w_x)^T
// smem word map: AH[0..2048), AL[2048..4096), B ch planes 4096+ch*2048 (5x),
//                weights at 14336 (5*64). Total 14656 words = 57.25 KB.
// All fragments pre-swizzled: one uint4 per lane per (tilegroup, kstep).
// ============================================================================
#define SC_SMEM_BYTES (14656*4)

__global__ __launch_bounds__(256, 2)
void scores_tc_kernel(const float* __restrict__ pos, float* __restrict__ attn)
{
    extern __shared__ float sm[];
    uint32_t* smu = reinterpret_cast<uint32_t*>(sm);
    float* sw = sm + 14336;

    int tid  = threadIdx.x;
    int lane = tid & 31, warp = tid >> 5;
    int wm = warp >> 2, wn = warp & 3;          // wm: j-half, wn: i-group
    int qr = lane >> 2, qc = lane & 3;
    int i0 = blockIdx.x << 5, j0 = blockIdx.y << 6;
    int z  = blockIdx.z;                        // b*NH + h
    int bbx = z >> 3;

    if (tid < DK) {
        #pragma unroll
        for (int p = 0; p < 4; p++) sw[p*64 + tid] = g_Mmat[tid*4+p];
        sw[4*64 + tid] = g_cvec[tid];
    }

    // ---- build A: K tile 64j x 64d, hi/lo bf16, fragment-swizzled ----
    {
        int j = tid >> 2, tq = tid & 3;
        const float* kp = g_k + ((size_t)z*NSEQ + j0 + j)*DK;
        int qrj = j & 7, jhalf = (j >> 3) & 1, mg = j >> 4;
        #pragma unroll
        for (int u = 0; u < 8; u++) {
            int d0 = 2*(tq + u*4);
            float2 kv = *(const float2*)(kp + d0);
            float h0 = bfhi(kv.x), h1 = bfhi(kv.y);
            int ks = d0 >> 4, kk = d0 & 15, qcc = (kk >> 1) & 3, khalf = kk >> 3;
            int base = (((mg*4 + ks)*32) + qrj*4 + qcc)*4 + (jhalf + 2*khalf);
            smu[base]        = pkbf2(h0, h1);
            smu[2048 + base] = pkbf2(kv.x - h0, kv.y - h1);
        }
    }
    __syncthreads();   // weights visible for B build

    // ---- build B: Q' channels, 32i x 64d, hi/lo packed in uint4 ----
    {
        int i = tid >> 3, tq = tid & 7;
        const float* qp = g_q + ((size_t)z*NSEQ + i0 + i)*DK;
        int qri = i & 7, ng = i >> 3;
        #pragma unroll
        for (int u = 0; u < 4; u++) {
            int d0 = 2*(tq + u*8);
            float2 qv = *(const float2*)(qp + d0);
            int ks = d0 >> 4, kk = d0 & 15, qcc = (kk >> 1) & 3, khalf = kk >> 3;
            int fb = (((ng*4 + ks)*32) + qri*4 + qcc)*4;
            #pragma unroll
            for (int ch = 0; ch < 5; ch++) {
                float p0 = qv.x * sw[ch*64 + d0];
                float p1 = qv.y * sw[ch*64 + d0 + 1];
                float h0 = bfhi(p0), h1 = bfhi(p1);
                int ba = 4096 + ch*2048 + fb;
                smu[ba + khalf]     = pkbf2(h0, h1);
                smu[ba + 2 + khalf] = pkbf2(p0 - h0, p1 - h1);
            }
        }
    }
    __syncthreads();

    // ---- mma mainloop: 4 k16-steps over d=64 ----
    float acc[5][2][4];
    #pragma unroll
    for (int ch = 0; ch < 5; ch++)
        #pragma unroll
        for (int mt = 0; mt < 2; mt++)
            #pragma unroll
            for (int c = 0; c < 4; c++) acc[ch][mt][c] = 0.f;

    #pragma unroll
    for (int ks = 0; ks < 4; ks++) {
        uint4 ah[2], al[2];
        #pragma unroll
        for (int mt = 0; mt < 2; mt++) {
            int off = (((wm*2 + mt)*4 + ks)*32 + lane)*4;
            ah[mt] = *(const uint4*)&smu[off];
            al[mt] = *(const uint4*)&smu[2048 + off];
        }
        #pragma unroll
        for (int ch = 0; ch < 5; ch++) {
            uint4 bq = *(const uint4*)&smu[4096 + ch*2048 + ((wn*4 + ks)*32 + lane)*4];
            #pragma unroll
            for (int mt = 0; mt < 2; mt++) {
                mma_bf16(acc[ch][mt], ah[mt], bq.x, bq.y);   // Kh * Q'h
                mma_bf16(acc[ch][mt], ah[mt], bq.z, bq.w);   // Kh * Q'l
                mma_bf16(acc[ch][mt], al[mt], bq.x, bq.y);   // Kl * Q'h
            }
        }
    }

    // ---- epilogue: combine 5 channels with pos, scale, store ----
    #pragma unroll
    for (int mt = 0; mt < 2; mt++) {
        int colb = i0 + wn*8 + 2*qc;
        #pragma unroll
        for (int hf = 0; hf < 2; hf++) {
            int row = j0 + wm*32 + mt*16 + qr + 8*hf;
            const float* pp = pos + (((size_t)(bbx*NSEQ + row))*NSEQ + colb)*4;
            float4 p0 = *(const float4*)pp;
            float4 p1 = *(const float4*)(pp + 4);
            int c = 2*hf;
            float s0 = acc[4][mt][c]
                     + p0.x*acc[0][mt][c] + p0.y*acc[1][mt][c]
                     + p0.z*acc[2][mt][c] + p0.w*acc[3][mt][c];
            float s1 = acc[4][mt][c+1]
                     + p1.x*acc[0][mt][c+1] + p1.y*acc[1][mt][c+1]
                     + p1.z*acc[2][mt][c+1] + p1.w*acc[3][mt][c+1];
            *(float2*)(attn + ((size_t)z*NSEQ + row)*NSEQ + colb) =
                make_float2(s0*INV_T, s1*INV_T);
        }
    }
}

// ---------------- softmax over last axis, in place ---------------------------
__global__ __launch_bounds__(256)
void softmax_kernel(float* __restrict__ attn)
{
    size_t row = blockIdx.x;
    float* p = attn + row * NSEQ;
    int tid = threadIdx.x;
    __shared__ float redm[8];
    __shared__ float reds[8];

    float v0 = p[tid], v1 = p[tid + 256];
    float m = warp_max(fmaxf(v0, v1));
    if ((tid & 31) == 0) redm[tid >> 5] = m;
    __syncthreads();
    m = redm[0];
    #pragma unroll
    for (int w = 1; w < 8; w++) m = fmaxf(m, redm[w]);

    float e0 = __expf(v0 - m), e1 = __expf(v1 - m);
    float s = warp_sum(e0 + e1);
    if ((tid & 31) == 0) reds[tid >> 5] = s;
    __syncthreads();
    s = reds[0];
    #pragma unroll
    for (int w = 1; w < 8; w++) s += reds[w];

    float inv = 1.0f / s;
    p[tid]       = e0 * inv;
    p[tid + 256] = e1 * inv;
}

// ---------------- layer norm (one token per block) ---------------------------
__global__ __launch_bounds__(256)
void layernorm_kernel(const float* __restrict__ x, const float* __restrict__ gam,
                      const float* __restrict__ bet, float* __restrict__ out)
{
    int t = blockIdx.x, tid = threadIdx.x;
    const float* xr = x + (size_t)t * DMODEL;
    __shared__ float red[8];

    float a0 = xr[tid], a1 = xr[tid + 256];
    float s = warp_sum(a0 + a1);
    if ((tid & 31) == 0) red[tid >> 5] = s;
    __syncthreads();
    s = red[0];
    #pragma unroll
    for (int w = 1; w < 8; w++) s += red[w];
    float mu = s * (1.0f / DMODEL);
    float d0 = a0 - mu, d1 = a1 - mu;
    __syncthreads();

    float q = warp_sum(d0*d0 + d1*d1);
    if ((tid & 31) == 0) red[tid >> 5] = q;
    __syncthreads();
    q = red[0];
    #pragma unroll
    for (int w = 1; w < 8; w++) q += red[w];
    float inv = rsqrtf(q * (1.0f / DMODEL) + LN_EPS);

    float* orow = out + (size_t)t * DMODEL;
    orow[tid]       = d0 * inv * gam[tid]       + bet[tid];
    orow[tid + 256] = d1 * inv * gam[tid + 256] + bet[tid + 256];
}

// ---------------- launch -----------------------------------------------------
extern "C" void kernel_launch(void* const* d_in, const int* in_sizes, int n_in,
                              void* d_out, int out_size)
{
    (void)in_sizes; (void)n_in; (void)out_size;
    const float* enc    = (const float*)d_in[0];
    const float* pos    = (const float*)d_in[1];
    const float* w_qs   = (const float*)d_in[2];
    const float* w_ks   = (const float*)d_in[3];
    const float* w_vs   = (const float*)d_in[4];
    const float* w_fc   = (const float*)d_in[5];
    const float* rp_w1  = (const float*)d_in[6];
    const float* rp_b1  = (const float*)d_in[7];
    const float* rp_w2  = (const float*)d_in[8];
    const float* rp_b2  = (const float*)d_in[9];
    const float* ln1_g  = (const float*)d_in[10];
    const float* ln1_b  = (const float*)d_in[11];
    const float* ln2_g  = (const float*)d_in[12];
    const float* ln2_b  = (const float*)d_in[13];
    const float* ffn_w1 = (const float*)d_in[14];
    const float* ffn_b1 = (const float*)d_in[15];
    const float* ffn_w2 = (const float*)d_in[16];
    const float* ffn_b2 = (const float*)d_in[17];

    float* out2 = (float*)d_out;                          // [4,512,512]
    float* attn = out2 + (size_t)TOK * DMODEL;            // [4,8,512,512]

    float *pv, *pheads, *ptmp1, *pln1, *pffh, *ptmp2;
    cudaGetSymbolAddress((void**)&pv,     g_v);
    cudaGetSymbolAddress((void**)&pheads, g_heads);
    cudaGetSymbolAddress((void**)&ptmp1,  g_tmp1);
    cudaGetSymbolAddress((void**)&pln1,   g_ln1);
    cudaGetSymbolAddress((void**)&pffh,   g_ffh);
    cudaGetSymbolAddress((void**)&ptmp2,  g_tmp2);

    cudaFuncSetAttribute(scores_tc_kernel,
                         cudaFuncAttributeMaxDynamicSharedMemorySize, SC_SMEM_BYTES);

    // 1) collapse rel-pos MLP
    rp_combine_kernel<<<1, 64>>>(rp_w1, rp_b1, rp_w2, rp_b2);

    // 2+3) QKV projection, 3xTF32 split, two column halves
    {
        dim3 g(6, TOK/128, 1);
        qkv3_kernel<<<g, 256>>>(enc, w_qs, w_ks, w_vs, 0);
        qkv3_kernel<<<g, 256>>>(enc, w_qs, w_ks, w_vs, 768);
    }

    // 4) relative-position attention logits on tensor cores (bf16 3-term)
    {
        dim3 g(NSEQ/32, NSEQ/64, BB*NH);   // (16, 8, 32) = 4096 blocks
        scores_tc_kernel<<<g, 256, SC_SMEM_BYTES>>>(pos, attn);
    }

    // 5) softmax in place
    softmax_kernel<<<BB*NH*NSEQ, 256>>>(attn);

    // 6) AV (tf32): per (b,h): P[512,512] @ V[512,64] -> g_heads
    {
        dim3 g(1, NSEQ/128, BB*NH);
        tgemm_kernel<64, 2, false, false, false, false><<<g, 256>>>(
            attn, pv, nullptr, nullptr, nullptr,
            DK, NSEQ, (size_t)NSEQ*NSEQ, (size_t)NSEQ*DK);
    }

    // 7) fc + residual(enc) -> g_tmp1 (tf32); LN1
    {
        dim3 g(DMODEL/64, TOK/128, 1);
        tgemm_kernel<64, 0, true, false, false, true><<<g, 256>>>(
            pheads, w_fc, nullptr, enc, ptmp1, DMODEL, DMODEL, 0, 0);
    }
    layernorm_kernel<<<TOK, 256>>>(ptmp1, ln1_g, ln1_b, pln1);

    // 8) FFN1 (tf32): relu(ln1 @ W1^T + b1) -> g_ffh
    {
        dim3 g(DINNER/128, TOK/128, 1);
        tgemm_kernel<128, 0, true, true, true, false><<<g, 256>>>(
            pln1, ffn_w1, ffn_b1, nullptr, pffh, DINNER, DMODEL, 0, 0);
    }

    // 9) FFN2 (tf32): ffh @ W2^T + b2 + ln1 -> g_tmp2
    {
        dim3 g(DMODEL/64, TOK/128, 1);
        tgemm_kernel<64, 0, true, true, false, true><<<g, 256>>>(
            pffh, ffn_w2, ffn_b2, pln1, ptmp2, DMODEL, DINNER, 0, 0);
    }

    // 10) LN2 -> out2
    layernorm_kernel<<<TOK, 256>>>(ptmp2, ln2_g, ln2_b, out2);
}

// round 13
// speedup vs baseline: 1.1047x; 1.0162x over previous
#include <cuda_runtime.h>
#include <cuda_bf16.h>
#include <math.h>
#include <stdint.h>

#define BB      4
#define NSEQ    512
#define DMODEL  512
#define NH      8
#define DK      64
#define TOK     (BB*NSEQ)      // 2048
#define DINNER  2048
#define LN_EPS  1e-6f
#define INV_T   0.125f         // 1/sqrt(64)

// ---------------- scratch ----------------------------------------------------
__device__ float g_q[BB*NH*NSEQ*DK];        // [b,h,n,d]
__device__ float g_k[BB*NH*NSEQ*DK];        // [b,h,n,d]
__device__ float g_v[BB*NH*NSEQ*DK];        // [b,h,n,d]
__device__ float g_Mmat[DK*4];              // combined rp matrix  M[d][p]
__device__ float g_cvec[DK];                // combined rp bias    c[d]
__device__ float g_heads[TOK*DMODEL];       // [b,n, h*dv]
__device__ float g_tmp1[TOK*DMODEL];
__device__ float g_ln1[TOK*DMODEL];
__device__ float g_ffh[TOK*DINNER];
__device__ float g_tmp2[TOK*DMODEL];

// pre-converted bf16 fragment planes for the scores kernel
// g_kfrag: per (z, jg): 512 uint4 hi + 512 uint4 lo  (frag idx = mg*128+ks*32+lane)
// g_qfrag: per (z, ig, ch): 512 uint4 {hi_klo, hi_khi, lo_klo, lo_khi}
__device__ uint4 g_kfrag[32*8*1024];        // 4 MB
__device__ uint4 g_qfrag[32*16*5*512];      // 21 MB

// ---------------- helpers ----------------------------------------------------
__device__ __forceinline__ float warp_sum(float v) {
    #pragma unroll
    for (int o = 16; o; o >>= 1) v += __shfl_xor_sync(0xffffffffu, v, o);
    return v;
}
__device__ __forceinline__ float warp_max(float v) {
    #pragma unroll
    for (int o = 16; o; o >>= 1) v = fmaxf(v, __shfl_xor_sync(0xffffffffu, v, o));
    return v;
}
__device__ __forceinline__ float to_tf32(float x) {
    uint32_t u;
    asm("cvt.rna.tf32.f32 %0, %1;" : "=r"(u) : "f"(x));
    return __uint_as_float(u);
}
__device__ __forceinline__ void mma_tf32(float (&c)[4], const uint32_t (&a)[4],
                                         const uint32_t (&b)[2]) {
    asm volatile(
        "mma.sync.aligned.m16n8k8.row.col.f32.tf32.tf32.f32 "
        "{%0,%1,%2,%3}, {%4,%5,%6,%7}, {%8,%9}, {%0,%1,%2,%3};\n"
        : "+f"(c[0]), "+f"(c[1]), "+f"(c[2]), "+f"(c[3])
        : "r"(a[0]), "r"(a[1]), "r"(a[2]), "r"(a[3]), "r"(b[0]), "r"(b[1]));
}
__device__ __forceinline__ void mma_bf16(float (&c)[4], const uint4& a,
                                         uint32_t b0, uint32_t b1) {
    asm volatile(
        "mma.sync.aligned.m16n8k16.row.col.f32.bf16.bf16.f32 "
        "{%0,%1,%2,%3}, {%4,%5,%6,%7}, {%8,%9}, {%0,%1,%2,%3};\n"
        : "+f"(c[0]), "+f"(c[1]), "+f"(c[2]), "+f"(c[3])
        : "r"(a.x), "r"(a.y), "r"(a.z), "r"(a.w), "r"(b0), "r"(b1));
}
__device__ __forceinline__ uint32_t pkbf2(float x0, float x1) {
    __nv_bfloat162 v = __floats2bfloat162_rn(x0, x1);
    return *reinterpret_cast<uint32_t*>(&v);
}
__device__ __forceinline__ float bfhi(float x) {
    return __bfloat162float(__float2bfloat16(x));
}

// ---------------- collapse rel-pos MLP: M = W2@W1, c = W2@b1 + b2 -----------
__global__ void rp_combine_kernel(const float* __restrict__ w1, const float* __restrict__ b1,
                                  const float* __restrict__ w2, const float* __restrict__ b2) {
    int d = threadIdx.x;
    if (d >= DK) return;
    float m0 = 0.f, m1 = 0.f, m2 = 0.f, m3 = 0.f, cc = 0.f;
    for (int k = 0; k < DK; k++) {
        float w = w2[d*DK + k];
        m0 = fmaf(w, w1[k*4+0], m0);
        m1 = fmaf(w, w1[k*4+1], m1);
        m2 = fmaf(w, w1[k*4+2], m2);
        m3 = fmaf(w, w1[k*4+3], m3);
        cc = fmaf(w, b1[k],      cc);
    }
    g_Mmat[d*4+0] = m0; g_Mmat[d*4+1] = m1;
    g_Mmat[d*4+2] = m2; g_Mmat[d*4+3] = m3;
    g_cvec[d] = cc + b2[d];
}

// ============================================================================
// QKV projection via 3xTF32 split MMA (fp32-grade accuracy on tensor cores).
// ============================================================================
__global__ __launch_bounds__(256)
void qkv3_kernel(const float* __restrict__ A,
                 const float* __restrict__ B0, const float* __restrict__ B1,
                 const float* __restrict__ B2, int colbase)
{
    const int K = DMODEL;
    __shared__ __align__(16) float Ah[2][8][136], Al[2][8][136];
    __shared__ __align__(16) float Bh[2][8][136], Bl[2][8][136];

    int tid  = threadIdx.x;
    int lane = tid & 31, warp = tid >> 5;
    int wm = warp >> 2, wn = warp & 3;
    int qr = lane >> 2, qc = lane & 3;
    int row0 = blockIdx.y << 7;
    int col0 = colbase + (blockIdx.x << 7);

    int wsel = col0 >> 9;
    const float* Bw = (wsel == 0) ? B0 : ((wsel == 1) ? B1 : B2);
    const float* Bb = Bw + (size_t)(col0 & 511) * K;

    int ar = tid >> 1, ak4 = (tid & 1) << 2;
    const float* Ald = A + (size_t)(row0 + ar) * K + ak4;
    const float* Bld = Bb + (size_t)ar * K + ak4;

    float acc[4][4][4];
    #pragma unroll
    for (int mt = 0; mt < 4; mt++)
        #pragma unroll
        for (int nt = 0; nt < 4; nt++)
            #pragma unroll
            for (int c = 0; c < 4; c++) acc[mt][nt][c] = 0.f;

    float4 av, bv;
    auto ldG = [&](int k0) {
        av = *(const float4*)(Ald + k0);
        bv = *(const float4*)(Bld + k0);
    };
    auto stS = [&](int buf) {
        const float* ap = (const float*)&av;
        const float* bp = (const float*)&bv;
        #pragma unroll
        for (int e = 0; e < 4; e++) {
            float x = ap[e], h = to_tf32(x);
            Ah[buf][ak4+e][ar] = h;
            Al[buf][ak4+e][ar] = to_tf32(x - h);
            float y = bp[e], g = to_tf32(y);
            Bh[buf][ak4+e][ar] = g;
            Bl[buf][ak4+e][ar] = to_tf32(y - g);
        }
    };
    auto compute = [&](int buf) {
        uint32_t afh[4][4], afl[4][4], bfh[4][2], bfl[4][2];
        #pragma unroll
        for (int mt = 0; mt < 4; mt++) {
            int mb = wm * 64 + mt * 16;
            afh[mt][0] = __float_as_uint(Ah[buf][qc  ][mb+qr  ]);
            afh[mt][1] = __float_as_uint(Ah[buf][qc  ][mb+qr+8]);
            afh[mt][2] = __float_as_uint(Ah[buf][qc+4][mb+qr  ]);
            afh[mt][3] = __float_as_uint(Ah[buf][qc+4][mb+qr+8]);
            afl[mt][0] = __float_as_uint(Al[buf][qc  ][mb+qr  ]);
            afl[mt][1] = __float_as_uint(Al[buf][qc  ][mb+qr+8]);
            afl[mt][2] = __float_as_uint(Al[buf][qc+4][mb+qr  ]);
            afl[mt][3] = __float_as_uint(Al[buf][qc+4][mb+qr+8]);
        }
        #pragma unroll
        for (int nt = 0; nt < 4; nt++) {
            int nb = wn * 32 + nt * 8;
            bfh[nt][0] = __float_as_uint(Bh[buf][qc  ][nb+qr]);
            bfh[nt][1] = __float_as_uint(Bh[buf][qc+4][nb+qr]);
            bfl[nt][0] = __float_as_uint(Bl[buf][qc  ][nb+qr]);
            bfl[nt][1] = __float_as_uint(Bl[buf][qc+4][nb+qr]);
        }
        #pragma unroll
        for (int mt = 0; mt < 4; mt++)
            #pragma unroll
            for (int nt = 0; nt < 4; nt++) {
                mma_tf32(acc[mt][nt], afh[mt], bfh[nt]);
                mma_tf32(acc[mt][nt], afh[mt], bfl[nt]);
                mma_tf32(acc[mt][nt], afl[mt], bfh[nt]);
            }
    };

    ldG(0);
    stS(0);
    __syncthreads();
    int buf = 0;
    for (int k0 = 8; k0 < K; k0 += 8) {
        ldG(k0);
        compute(buf);
        stS(buf ^ 1);
        __syncthreads();
        buf ^= 1;
    }
    compute(buf);

    #pragma unroll
    for (int mt = 0; mt < 4; mt++) {
        int rbase = row0 + wm * 64 + mt * 16 + qr;
        #pragma unroll
        for (int nt = 0; nt < 4; nt++) {
            int c = col0 + wn * 32 + nt * 8 + 2 * qc;
            int ws = c >> 9, cc = c & 511;
            int h = cc >> 6, d = cc & 63;
            float* dst = (ws == 0) ? g_q : ((ws == 1) ? g_k : g_v);
            #pragma unroll
            for (int hh = 0; hh < 2; hh++) {
                int r = rbase + hh * 8;
                int b = r >> 9, n = r & 511;
                float2 v = make_float2(acc[mt][nt][2*hh], acc[mt][nt][2*hh+1]);
                *(float2*)(dst + ((((size_t)b * NH + h) * NSEQ) + n) * DK + d) = v;
            }
        }
    }
}

// ============================================================================
// TF32 tensor-core GEMM (AV, fc, FFN1, FFN2)
// ============================================================================
template<int TN, int MAP, bool BTRANS, bool BIAS, bool RELU, bool RESID>
__global__ __launch_bounds__(256)
void tgemm_kernel(const float* __restrict__ A, const float* __restrict__ B0,
                  const float* __restrict__ bias, const float* __restrict__ resid,
                  float* __restrict__ C, int N, int K,
                  size_t strideA, size_t strideB)
{
    constexpr int NT   = TN / 32;
    constexpr int WN   = TN / 4;
    constexpr int BPAD = (TN == 128) ? 136 : 72;

    __shared__ __align__(16) float As[2][16][136];
    __shared__ __align__(16) float Bs[2][16][BPAD];

    int tid  = threadIdx.x;
    int lane = tid & 31, warp = tid >> 5;
    int wm = warp >> 2, wn = warp & 3;
    int qr = lane >> 2, qc = lane & 3;
    int row0 = blockIdx.y << 7;
    int col0 = blockIdx.x * TN;
    int z    = blockIdx.z;

    const float* Ab = A + (size_t)z * strideA;
    const float* Bb = BTRANS ? (B0 + (size_t)col0 * K)
                             : (B0 + (size_t)z * strideB + col0);

    int ar = tid >> 2, ak = (tid & 3) << 2;
    const float* Ald = Ab + (size_t)(row0 + ar) * K + ak;
    const float* Bld_t = Bb + (size_t)ar * K + ak;
    int bkr = tid >> 4, bn4 = (tid & 15) << 2;
    const float* Bld_n = Bb + (size_t)bkr * N + bn4;

    float acc[4][NT][4];
    #pragma unroll
    for (int mt = 0; mt < 4; mt++)
        #pragma unroll
        for (int nt = 0; nt < NT; nt++)
            #pragma unroll
            for (int c = 0; c < 4; c++) acc[mt][nt][c] = 0.f;

    float4 av[2], bv[2];
    auto ldG = [&](int k0) {
        av[0] = *(const float4*)(Ald + k0);
        av[1] = *(const float4*)(Ald + (size_t)64 * K + k0);
        if (BTRANS) {
            bv[0] = *(const float4*)(Bld_t + k0);
            if (TN == 128) bv[1] = *(const float4*)(Bld_t + (size_t)64 * K + k0);
        } else {
            bv[0] = *(const float4*)(Bld_n + (size_t)k0 * N);
        }
    };
    auto stS = [&](int buf) {
        #pragma unroll
        for (int h = 0; h < 2; h++) {
            int r = ar + h * 64;
            As[buf][ak+0][r] = to_tf32(((const float*)&av[h])[0]);
            As[buf][ak+1][r] = to_tf32(((const float*)&av[h])[1]);
            As[buf][ak+2][r] = to_tf32(((const float*)&av[h])[2]);
            As[buf][ak+3][r] = to_tf32(((const float*)&av[h])[3]);
        }
        if (BTRANS) {
            #pragma unroll
            for (int h = 0; h < (TN == 128 ? 2 : 1); h++) {
                int r = ar + h * 64;
                if (TN == 128 || r < TN) {
                    Bs[buf][ak+0][r] = to_tf32(((const float*)&bv[h])[0]);
                    Bs[buf][ak+1][r] = to_tf32(((const float*)&bv[h])[1]);
                    Bs[buf][ak+2][r] = to_tf32(((const float*)&bv[h])[2]);
                    Bs[buf][ak+3][r] = to_tf32(((const float*)&bv[h])[3]);
                }
            }
        } else {
            float4 t = make_float4(to_tf32(bv[0].x), to_tf32(bv[0].y),
                                   to_tf32(bv[0].z), to_tf32(bv[0].w));
            *(float4*)&Bs[buf][bkr][bn4] = t;
        }
    };
    auto compute = [&](int buf) {
        #pragma unroll
        for (int ks = 0; ks < 2; ks++) {
            int kb = ks * 8;
            uint32_t af[4][4], bf[NT][2];
            #pragma unroll
            for (int mt = 0; mt < 4; mt++) {
                int mb = wm * 64 + mt * 16;
                af[mt][0] = __float_as_uint(As[buf][kb+qc  ][mb+qr  ]);
                af[mt][1] = __float_as_uint(As[buf][kb+qc  ][mb+qr+8]);
                af[mt][2] = __float_as_uint(As[buf][kb+qc+4][mb+qr  ]);
                af[mt][3] = __float_as_uint(As[buf][kb+qc+4][mb+qr+8]);
            }
            #pragma unroll
            for (int nt = 0; nt < NT; nt++) {
                int nb = wn * WN + nt * 8;
                bf[nt][0] = __float_as_uint(Bs[buf][kb+qc  ][nb+qr]);
                bf[nt][1] = __float_as_uint(Bs[buf][kb+qc+4][nb+qr]);
            }
            #pragma unroll
            for (int mt = 0; mt < 4; mt++)
                #pragma unroll
                for (int nt = 0; nt < NT; nt++)
                    mma_tf32(acc[mt][nt], af[mt], bf[nt]);
        }
    };

    ldG(0);
    stS(0);
    __syncthreads();
    int buf = 0;
    for (int k0 = 16; k0 < K; k0 += 16) {
        ldG(k0);
        compute(buf);
        stS(buf ^ 1);
        __syncthreads();
        buf ^= 1;
    }
    compute(buf);

    #pragma unroll
    for (int mt = 0; mt < 4; mt++) {
        int rbase = row0 + wm * 64 + mt * 16 + qr;
        #pragma unroll
        for (int nt = 0; nt < NT; nt++) {
            int cg = col0 + wn * WN + nt * 8 + 2 * qc;
            #pragma unroll
            for (int hh = 0; hh < 2; hh++) {
                int r = rbase + hh * 8;
                float2 v = make_float2(acc[mt][nt][2*hh], acc[mt][nt][2*hh+1]);
                if (BIAS) { v.x += bias[cg]; v.y += bias[cg+1]; }
                if (RESID) {
                    const float2 rz = *(const float2*)(resid + (size_t)r * N + cg);
                    v.x += rz.x; v.y += rz.y;
                }
                if (RELU) { v.x = fmaxf(v.x, 0.f); v.y = fmaxf(v.y, 0.f); }
                if (MAP == 0) {
                    *(float2*)(C + (size_t)r * N + cg) = v;
                } else {
                    int b = z >> 3, h2 = z & 7;
                    *(float2*)(g_heads + ((size_t)(b * NSEQ) + r) * DMODEL + h2 * DK + cg) = v;
                }
            }
        }
    }
}

// ============================================================================
// scores prep: convert K and the 5 Q' channels to bf16 hi/lo fragment planes
// ONCE (the round-12 kernel redid this 8-16x inside each scores block).
// grid (8, 32): blockIdx.x = row-group g (64 rows), blockIdx.y = z (b*NH+h).
// ============================================================================
__global__ __launch_bounds__(256)
void scores_prep_kernel()
{
    __shared__ float sw[320];
    int tid = threadIdx.x;
    int g = blockIdx.x, z = blockIdx.y;
    if (tid < DK) {
        #pragma unroll
        for (int p = 0; p < 4; p++) sw[p*64 + tid] = g_Mmat[tid*4+p];
        sw[256 + tid] = g_cvec[tid];
    }
    __syncthreads();

    // ---- K fragments (hi plane + lo plane), rows j = g*64 .. g*64+63 ----
    {
        int jl = tid >> 2, tq = tid & 3;
        const float* kp = g_k + ((size_t)z*NSEQ + g*64 + jl)*DK;
        uint32_t* dst = reinterpret_cast<uint32_t*>(g_kfrag) + (size_t)(z*8 + g)*4096;
        int qrj = jl & 7, jhalf = (jl >> 3) & 1, mg = jl >> 4;
        #pragma unroll
        for (int u = 0; u < 8; u++) {
            int d0 = 2*(tq + u*4);
            float2 kv = *(const float2*)(kp + d0);
            float h0 = bfhi(kv.x), h1 = bfhi(kv.y);
            int ks = d0 >> 4, kk = d0 & 15, qcc = (kk >> 1) & 3, khalf = kk >> 3;
            int base = ((mg*4 + ks)*32 + qrj*4 + qcc)*4 + (jhalf + 2*khalf);
            dst[base]        = pkbf2(h0, h1);
            dst[2048 + base] = pkbf2(kv.x - h0, kv.y - h1);
        }
    }

    // ---- Q' channel fragments, rows i = g*64 .. g*64+63 (two 32-wide igs) ----
    {
        int il = tid >> 2, tq = tid & 3;
        int ig = g*2 + (il >> 5), iin = il & 31;
        const float* qp = g_q + ((size_t)z*NSEQ + g*64 + il)*DK;
        int qri = iin & 7, ng = iin >> 3;
        uint32_t* bd0 = reinterpret_cast<uint32_t*>(g_qfrag)
                      + (size_t)(z*16 + ig)*5*2048;
        #pragma unroll
        for (int u = 0; u < 8; u++) {
            int d0 = 2*(tq + u*4);
            float2 qv = *(const float2*)(qp + d0);
            int ks = d0 >> 4, kk = d0 & 15, qcc = (kk >> 1) & 3, khalf = kk >> 3;
            int fb = ((ng*4 + ks)*32 + qri*4 + qcc)*4;
            #pragma unroll
            for (int ch = 0; ch < 5; ch++) {
                float p0 = qv.x * sw[ch*64 + d0];
                float p1 = qv.y * sw[ch*64 + d0 + 1];
                float h0 = bfhi(p0), h1 = bfhi(p1);
                uint32_t* bd = bd0 + ch*2048;
                bd[fb + khalf]     = pkbf2(h0, h1);
                bd[fb + 2 + khalf] = pkbf2(p0 - h0, p1 - h1);
            }
        }
    }
}

// ============================================================================
// scores v5: smem-free, sync-free; fragments read directly from gmem planes.
// attn[b,h,j,i] = (1/T)*( S_c + sum_p pos[b,j,i,p]*S_p ),  S_x = K @ (q.*w_x)^T
// Block = 64j x 32i of one (b,h); 8 warps; bf16 3-term compensated m16n8k16.
// ============================================================================
__global__ __launch_bounds__(256)
void scores_tc_kernel(const float* __restrict__ pos, float* __restrict__ attn)
{
    int tid  = threadIdx.x;
    int lane = tid & 31, warp = tid >> 5;
    int wm = warp >> 2, wn = warp & 3;
    int qr = lane >> 2, qc = lane & 3;
    int ig = blockIdx.x, jg = blockIdx.y, z = blockIdx.z;
    int i0 = ig << 5, j0 = jg << 6;
    int bbx = z >> 3;

    const uint4* Af = g_kfrag + (size_t)(z*8 + jg)*1024;
    const uint4* Bf = g_qfrag + (size_t)(z*16 + ig)*2560 + wn*128 + lane;

    float acc[5][2][4];
    #pragma unroll
    for (int ch = 0; ch < 5; ch++)
        #pragma unroll
        for (int mt = 0; mt < 2; mt++)
            #pragma unroll
            for (int c = 0; c < 4; c++) acc[ch][mt][c] = 0.f;

    #pragma unroll
    for (int ks = 0; ks < 4; ks++) {
        uint4 ah[2], al[2];
        #pragma unroll
        for (int mt = 0; mt < 2; mt++) {
            int fi = (wm*2 + mt)*128 + ks*32 + lane;
            ah[mt] = __ldg(&Af[fi]);
            al[mt] = __ldg(&Af[512 + fi]);
        }
        #pragma unroll
        for (int ch = 0; ch < 5; ch++) {
            uint4 bq = __ldg(&Bf[ch*512 + ks*32]);
            #pragma unroll
            for (int mt = 0; mt < 2; mt++) {
                mma_bf16(acc[ch][mt], ah[mt], bq.x, bq.y);   // Kh * Q'h
                mma_bf16(acc[ch][mt], ah[mt], bq.z, bq.w);   // Kh * Q'l
                mma_bf16(acc[ch][mt], al[mt], bq.x, bq.y);   // Kl * Q'h
            }
        }
    }

    // ---- epilogue: combine 5 channels with pos, scale, store ----
    #pragma unroll
    for (int mt = 0; mt < 2; mt++) {
        int colb = i0 + wn*8 + 2*qc;
        #pragma unroll
        for (int hf = 0; hf < 2; hf++) {
            int row = j0 + wm*32 + mt*16 + qr + 8*hf;
            const float* pp = pos + (((size_t)(bbx*NSEQ + row))*NSEQ + colb)*4;
            float4 p0 = *(const float4*)pp;
            float4 p1 = *(const float4*)(pp + 4);
            int c = 2*hf;
            float s0 = acc[4][mt][c]
                     + p0.x*acc[0][mt][c] + p0.y*acc[1][mt][c]
                     + p0.z*acc[2][mt][c] + p0.w*acc[3][mt][c];
            float s1 = acc[4][mt][c+1]
                     + p1.x*acc[0][mt][c+1] + p1.y*acc[1][mt][c+1]
                     + p1.z*acc[2][mt][c+1] + p1.w*acc[3][mt][c+1];
            *(float2*)(attn + ((size_t)z*NSEQ + row)*NSEQ + colb) =
                make_float2(s0*INV_T, s1*INV_T);
        }
    }
}

// ---------------- softmax over last axis, in place ---------------------------
__global__ __launch_bounds__(256)
void softmax_kernel(float* __restrict__ attn)
{
    size_t row = blockIdx.x;
    float* p = attn + row * NSEQ;
    int tid = threadIdx.x;
    __shared__ float redm[8];
    __shared__ float reds[8];

    float v0 = p[tid], v1 = p[tid + 256];
    float m = warp_max(fmaxf(v0, v1));
    if ((tid & 31) == 0) redm[tid >> 5] = m;
    __syncthreads();
    m = redm[0];
    #pragma unroll
    for (int w = 1; w < 8; w++) m = fmaxf(m, redm[w]);

    float e0 = __expf(v0 - m), e1 = __expf(v1 - m);
    float s = warp_sum(e0 + e1);
    if ((tid & 31) == 0) reds[tid >> 5] = s;
    __syncthreads();
    s = reds[0];
    #pragma unroll
    for (int w = 1; w < 8; w++) s += reds[w];

    float inv = 1.0f / s;
    p[tid]       = e0 * inv;
    p[tid + 256] = e1 * inv;
}

// ---------------- layer norm (one token per block) ---------------------------
__global__ __launch_bounds__(256)
void layernorm_kernel(const float* __restrict__ x, const float* __restrict__ gam,
                      const float* __restrict__ bet, float* __restrict__ out)
{
    int t = blockIdx.x, tid = threadIdx.x;
    const float* xr = x + (size_t)t * DMODEL;
    __shared__ float red[8];

    float a0 = xr[tid], a1 = xr[tid + 256];
    float s = warp_sum(a0 + a1);
    if ((tid & 31) == 0) red[tid >> 5] = s;
    __syncthreads();
    s = red[0];
    #pragma unroll
    for (int w = 1; w < 8; w++) s += red[w];
    float mu = s * (1.0f / DMODEL);
    float d0 = a0 - mu, d1 = a1 - mu;
    __syncthreads();

    float q = warp_sum(d0*d0 + d1*d1);
    if ((tid & 31) == 0) red[tid >> 5] = q;
    __syncthreads();
    q = red[0];
    #pragma unroll
    for (int w = 1; w < 8; w++) q += red[w];
    float inv = rsqrtf(q * (1.0f / DMODEL) + LN_EPS);

    float* orow = out + (size_t)t * DMODEL;
    orow[tid]       = d0 * inv * gam[tid]       + bet[tid];
    orow[tid + 256] = d1 * inv * gam[tid + 256] + bet[tid + 256];
}

// ---------------- launch -----------------------------------------------------
extern "C" void kernel_launch(void* const* d_in, const int* in_sizes, int n_in,
                              void* d_out, int out_size)
{
    (void)in_sizes; (void)n_in; (void)out_size;
    const float* enc    = (const float*)d_in[0];
    const float* pos    = (const float*)d_in[1];
    const float* w_qs   = (const float*)d_in[2];
    const float* w_ks   = (const float*)d_in[3];
    const float* w_vs   = (const float*)d_in[4];
    const float* w_fc   = (const float*)d_in[5];
    const float* rp_w1  = (const float*)d_in[6];
    const float* rp_b1  = (const float*)d_in[7];
    const float* rp_w2  = (const float*)d_in[8];
    const float* rp_b2  = (const float*)d_in[9];
    const float* ln1_g  = (const float*)d_in[10];
    const float* ln1_b  = (const float*)d_in[11];
    const float* ln2_g  = (const float*)d_in[12];
    const float* ln2_b  = (const float*)d_in[13];
    const float* ffn_w1 = (const float*)d_in[14];
    const float* ffn_b1 = (const float*)d_in[15];
    const float* ffn_w2 = (const float*)d_in[16];
    const float* ffn_b2 = (const float*)d_in[17];

    float* out2 = (float*)d_out;                          // [4,512,512]
    float* attn = out2 + (size_t)TOK * DMODEL;            // [4,8,512,512]

    float *pv, *pheads, *ptmp1, *pln1, *pffh, *ptmp2;
    cudaGetSymbolAddress((void**)&pv,     g_v);
    cudaGetSymbolAddress((void**)&pheads, g_heads);
    cudaGetSymbolAddress((void**)&ptmp1,  g_tmp1);
    cudaGetSymbolAddress((void**)&pln1,   g_ln1);
    cudaGetSymbolAddress((void**)&pffh,   g_ffh);
    cudaGetSymbolAddress((void**)&ptmp2,  g_tmp2);

    // 1) collapse rel-pos MLP
    rp_combine_kernel<<<1, 64>>>(rp_w1, rp_b1, rp_w2, rp_b2);

    // 2+3) QKV projection, 3xTF32 split, two column halves
    {
        dim3 g(6, TOK/128, 1);
        qkv3_kernel<<<g, 256>>>(enc, w_qs, w_ks, w_vs, 0);
        qkv3_kernel<<<g, 256>>>(enc, w_qs, w_ks, w_vs, 768);
    }

    // 4) one-time bf16 fragment conversion (K hi/lo + 5 Q' channels)
    {
        dim3 g(8, BB*NH);                  // (8, 32) = 256 blocks
        scores_prep_kernel<<<g, 256>>>();
    }

    // 5) relative-position attention logits on tensor cores (smem-free)
    {
        dim3 g(NSEQ/32, NSEQ/64, BB*NH);   // (16, 8, 32) = 4096 blocks
        scores_tc_kernel<<<g, 256>>>(pos, attn);
    }

    // 6) softmax in place
    softmax_kernel<<<BB*NH*NSEQ, 256>>>(attn);

    // 7) AV (tf32): per (b,h): P[512,512] @ V[512,64] -> g_heads
    {
        dim3 g(1, NSEQ/128, BB*NH);
        tgemm_kernel<64, 2, false, false, false, false><<<g, 256>>>(
            attn, pv, nullptr, nullptr, nullptr,
            DK, NSEQ, (size_t)NSEQ*NSEQ, (size_t)NSEQ*DK);
    }

    // 8) fc + residual(enc) -> g_tmp1 (tf32); LN1
    {
        dim3 g(DMODEL/64, TOK/128, 1);
        tgemm_kernel<64, 0, true, false, false, true><<<g, 256>>>(
            pheads, w_fc, nullptr, enc, ptmp1, DMODEL, DMODEL, 0, 0);
    }
    layernorm_kernel<<<TOK, 256>>>(ptmp1, ln1_g, ln1_b, pln1);

    // 9) FFN1 (tf32): relu(ln1 @ W1^T + b1) -> g_ffh
    {
        dim3 g(DINNER/128, TOK/128, 1);
        tgemm_kernel<128, 0, true, true, true, false><<<g, 256>>>(
            pln1, ffn_w1, ffn_b1, nullptr, pffh, DINNER, DMODEL, 0, 0);
    }

    // 10) FFN2 (tf32): ffh @ W2^T + b2 + ln1 -> g_tmp2
    {
        dim3 g(DMODEL/64, TOK/128, 1);
        tgemm_kernel<64, 0, true, true, false, true><<<g, 256>>>(
            pffh, ffn_w2, ffn_b2, pln1, ptmp2, DMODEL, DINNER, 0, 0);
    }

    // 11) LN2 -> out2
    layernorm_kernel<<<TOK, 256>>>(ptmp2, ln2_g, ln2_b, out2);
}

// round 15
// speedup vs baseline: 1.2817x; 1.1602x over previous
#include <cuda_runtime.h>
#include <cuda_bf16.h>
#include <math.h>
#include <stdint.h>

#define BB      4
#define NSEQ    512
#define DMODEL  512
#define NH      8
#define DK      64
#define TOK     (BB*NSEQ)      // 2048
#define DINNER  2048
#define LN_EPS  1e-6f
#define INV_T   0.125f         // 1/sqrt(64)

// ---------------- scratch ----------------------------------------------------
__device__ float g_q[BB*NH*NSEQ*DK];        // [b,h,n,d]
__device__ float g_k[BB*NH*NSEQ*DK];        // [b,h,n,d]
__device__ float g_v[BB*NH*NSEQ*DK];        // [b,h,n,d]
__device__ float g_Mmat[DK*4];              // combined rp matrix  M[d][p]
__device__ float g_cvec[DK];                // combined rp bias    c[d]
__device__ float g_heads[TOK*DMODEL];       // [b,n, h*dv]
__device__ float g_tmp1[TOK*DMODEL];
__device__ float g_ln1[TOK*DMODEL];
__device__ float g_ffh[TOK*DINNER];
__device__ float g_tmp2[TOK*DMODEL];

// pre-converted bf16 fragment planes for the scores kernel
__device__ uint4 g_kfrag[32*8*1024];        // 4 MB
__device__ uint4 g_qfrag[32*16*5*512];      // 21 MB

// ---------------- helpers ----------------------------------------------------
__device__ __forceinline__ float warp_sum(float v) {
    #pragma unroll
    for (int o = 16; o; o >>= 1) v += __shfl_xor_sync(0xffffffffu, v, o);
    return v;
}
__device__ __forceinline__ float warp_max(float v) {
    #pragma unroll
    for (int o = 16; o; o >>= 1) v = fmaxf(v, __shfl_xor_sync(0xffffffffu, v, o));
    return v;
}
__device__ __forceinline__ float to_tf32(float x) {
    uint32_t u;
    asm("cvt.rna.tf32.f32 %0, %1;" : "=r"(u) : "f"(x));
    return __uint_as_float(u);
}
__device__ __forceinline__ void mma_tf32(float (&c)[4], const uint32_t (&a)[4],
                                         const uint32_t (&b)[2]) {
    asm volatile(
        "mma.sync.aligned.m16n8k8.row.col.f32.tf32.tf32.f32 "
        "{%0,%1,%2,%3}, {%4,%5,%6,%7}, {%8,%9}, {%0,%1,%2,%3};\n"
        : "+f"(c[0]), "+f"(c[1]), "+f"(c[2]), "+f"(c[3])
        : "r"(a[0]), "r"(a[1]), "r"(a[2]), "r"(a[3]), "r"(b[0]), "r"(b[1]));
}
__device__ __forceinline__ void mma_bf16(float (&c)[4], const uint4& a,
                                         uint32_t b0, uint32_t b1) {
    asm volatile(
        "mma.sync.aligned.m16n8k16.row.col.f32.bf16.bf16.f32 "
        "{%0,%1,%2,%3}, {%4,%5,%6,%7}, {%8,%9}, {%0,%1,%2,%3};\n"
        : "+f"(c[0]), "+f"(c[1]), "+f"(c[2]), "+f"(c[3])
        : "r"(a.x), "r"(a.y), "r"(a.z), "r"(a.w), "r"(b0), "r"(b1));
}
__device__ __forceinline__ void mma_bf16r(float (&c)[4], const uint32_t (&a)[4],
                                          uint32_t b0, uint32_t b1) {
    asm volatile(
        "mma.sync.aligned.m16n8k16.row.col.f32.bf16.bf16.f32 "
        "{%0,%1,%2,%3}, {%4,%5,%6,%7}, {%8,%9}, {%0,%1,%2,%3};\n"
        : "+f"(c[0]), "+f"(c[1]), "+f"(c[2]), "+f"(c[3])
        : "r"(a[0]), "r"(a[1]), "r"(a[2]), "r"(a[3]), "r"(b0), "r"(b1));
}
__device__ __forceinline__ uint32_t pkbf2(float x0, float x1) {
    __nv_bfloat162 v = __floats2bfloat162_rn(x0, x1);
    return *reinterpret_cast<uint32_t*>(&v);
}
__device__ __forceinline__ float bfhi(float x) {
    return __bfloat162float(__float2bfloat16(x));
}

// ---------------- collapse rel-pos MLP: M = W2@W1, c = W2@b1 + b2 -----------
__global__ void rp_combine_kernel(const float* __restrict__ w1, const float* __restrict__ b1,
                                  const float* __restrict__ w2, const float* __restrict__ b2) {
    int d = threadIdx.x;
    if (d >= DK) return;
    float m0 = 0.f, m1 = 0.f, m2 = 0.f, m3 = 0.f, cc = 0.f;
    for (int k = 0; k < DK; k++) {
        float w = w2[d*DK + k];
        m0 = fmaf(w, w1[k*4+0], m0);
        m1 = fmaf(w, w1[k*4+1], m1);
        m2 = fmaf(w, w1[k*4+2], m2);
        m3 = fmaf(w, w1[k*4+3], m3);
        cc = fmaf(w, b1[k],      cc);
    }
    g_Mmat[d*4+0] = m0; g_Mmat[d*4+1] = m1;
    g_Mmat[d*4+2] = m2; g_Mmat[d*4+3] = m3;
    g_cvec[d] = cc + b2[d];
}

// ============================================================================
// QKV projection via 3-term compensated bf16 MMA (m16n8k16), fp32-grade.
// smem words hold packed bf16x2 (d-pairs); indexing identical to tf32 version
// with half the k-columns.
// ============================================================================
__global__ __launch_bounds__(256)
void qkv3_kernel(const float* __restrict__ A,
                 const float* __restrict__ B0, const float* __restrict__ B1,
                 const float* __restrict__ B2, int colbase)
{
    const int K = DMODEL;
    __shared__ uint32_t Ah[2][8][136], Al[2][8][136];
    __shared__ uint32_t Bh[2][8][136], Bl[2][8][136];

    int tid  = threadIdx.x;
    int lane = tid & 31, warp = tid >> 5;
    int wm = warp >> 2, wn = warp & 3;
    int qr = lane >> 2, qc = lane & 3;
    int row0 = blockIdx.y << 7;
    int col0 = colbase + (blockIdx.x << 7);

    int wsel = col0 >> 9;
    const float* Bw = (wsel == 0) ? B0 : ((wsel == 1) ? B1 : B2);
    const float* Bb = Bw + (size_t)(col0 & 511) * K;

    int ar = tid >> 1, aw = (tid & 1) << 2;     // word base (d base = aw*2)
    const float* Ald = A + (size_t)(row0 + ar) * K + aw*2;
    const float* Bld = Bb + (size_t)ar * K + aw*2;

    float acc[4][4][4];
    #pragma unroll
    for (int mt = 0; mt < 4; mt++)
        #pragma unroll
        for (int nt = 0; nt < 4; nt++)
            #pragma unroll
            for (int c = 0; c < 4; c++) acc[mt][nt][c] = 0.f;

    float4 av0, av1, bv0, bv1;
    auto ldG = [&](int k0) {
        av0 = *(const float4*)(Ald + k0);
        av1 = *(const float4*)(Ald + k0 + 4);
        bv0 = *(const float4*)(Bld + k0);
        bv1 = *(const float4*)(Bld + k0 + 4);
    };
    auto stS = [&](int buf) {
        const float* ap0 = (const float*)&av0;
        const float* ap1 = (const float*)&av1;
        const float* bp0 = (const float*)&bv0;
        const float* bp1 = (const float*)&bv1;
        #pragma unroll
        for (int w = 0; w < 4; w++) {
            float x0 = (w < 2) ? ap0[2*w]   : ap1[2*w-4];
            float x1 = (w < 2) ? ap0[2*w+1] : ap1[2*w-3];
            float h0 = bfhi(x0), h1 = bfhi(x1);
            Ah[buf][aw+w][ar] = pkbf2(h0, h1);
            Al[buf][aw+w][ar] = pkbf2(x0 - h0, x1 - h1);
            float y0 = (w < 2) ? bp0[2*w]   : bp1[2*w-4];
            float y1 = (w < 2) ? bp0[2*w+1] : bp1[2*w-3];
            float g0 = bfhi(y0), g1 = bfhi(y1);
            Bh[buf][aw+w][ar] = pkbf2(g0, g1);
            Bl[buf][aw+w][ar] = pkbf2(y0 - g0, y1 - g1);
        }
    };
    auto compute = [&](int buf) {
        uint32_t afh[4][4], afl[4][4], bfh[4][2], bfl[4][2];
        #pragma unroll
        for (int mt = 0; mt < 4; mt++) {
            int mb = wm * 64 + mt * 16;
            afh[mt][0] = Ah[buf][qc  ][mb+qr  ];
            afh[mt][1] = Ah[buf][qc  ][mb+qr+8];
            afh[mt][2] = Ah[buf][qc+4][mb+qr  ];
            afh[mt][3] = Ah[buf][qc+4][mb+qr+8];
            afl[mt][0] = Al[buf][qc  ][mb+qr  ];
            afl[mt][1] = Al[buf][qc  ][mb+qr+8];
            afl[mt][2] = Al[buf][qc+4][mb+qr  ];
            afl[mt][3] = Al[buf][qc+4][mb+qr+8];
        }
        #pragma unroll
        for (int nt = 0; nt < 4; nt++) {
            int nb = wn * 32 + nt * 8;
            bfh[nt][0] = Bh[buf][qc  ][nb+qr];
            bfh[nt][1] = Bh[buf][qc+4][nb+qr];
            bfl[nt][0] = Bl[buf][qc  ][nb+qr];
            bfl[nt][1] = Bl[buf][qc+4][nb+qr];
        }
        #pragma unroll
        for (int mt = 0; mt < 4; mt++)
            #pragma unroll
            for (int nt = 0; nt < 4; nt++) {
                mma_bf16r(acc[mt][nt], afh[mt], bfh[nt][0], bfh[nt][1]);
                mma_bf16r(acc[mt][nt], afh[mt], bfl[nt][0], bfl[nt][1]);
                mma_bf16r(acc[mt][nt], afl[mt], bfh[nt][0], bfh[nt][1]);
            }
    };

    ldG(0);
    stS(0);
    __syncthreads();
    int buf = 0;
    for (int k0 = 16; k0 < K; k0 += 16) {
        ldG(k0);
        compute(buf);
        stS(buf ^ 1);
        __syncthreads();
        buf ^= 1;
    }
    compute(buf);

    #pragma unroll
    for (int mt = 0; mt < 4; mt++) {
        int rbase = row0 + wm * 64 + mt * 16 + qr;
        #pragma unroll
        for (int nt = 0; nt < 4; nt++) {
            int c = col0 + wn * 32 + nt * 8 + 2 * qc;
            int ws = c >> 9, cc = c & 511;
            int h = cc >> 6, d = cc & 63;
            float* dst = (ws == 0) ? g_q : ((ws == 1) ? g_k : g_v);
            #pragma unroll
            for (int hh = 0; hh < 2; hh++) {
                int r = rbase + hh * 8;
                int b = r >> 9, n = r & 511;
                float2 v = make_float2(acc[mt][nt][2*hh], acc[mt][nt][2*hh+1]);
                *(float2*)(dst + ((((size_t)b * NH + h) * NSEQ) + n) * DK + d) = v;
            }
        }
    }
}

// ============================================================================
// TF32 tensor-core GEMM (AV, fc, FFN1, FFN2) — unchanged (error-budget owner).
// ============================================================================
template<int TN, int MAP, bool BTRANS, bool BIAS, bool RELU, bool RESID>
__global__ __launch_bounds__(256)
void tgemm_kernel(const float* __restrict__ A, const float* __restrict__ B0,
                  const float* __restrict__ bias, const float* __restrict__ resid,
                  float* __restrict__ C, int N, int K,
                  size_t strideA, size_t strideB)
{
    constexpr int NT   = TN / 32;
    constexpr int WN   = TN / 4;
    constexpr int BPAD = (TN == 128) ? 136 : 72;

    __shared__ __align__(16) float As[2][16][136];
    __shared__ __align__(16) float Bs[2][16][BPAD];

    int tid  = threadIdx.x;
    int lane = tid & 31, warp = tid >> 5;
    int wm = warp >> 2, wn = warp & 3;
    int qr = lane >> 2, qc = lane & 3;
    int row0 = blockIdx.y << 7;
    int col0 = blockIdx.x * TN;
    int z    = blockIdx.z;

    const float* Ab = A + (size_t)z * strideA;
    const float* Bb = BTRANS ? (B0 + (size_t)col0 * K)
                             : (B0 + (size_t)z * strideB + col0);

    int ar = tid >> 2, ak = (tid & 3) << 2;
    const float* Ald = Ab + (size_t)(row0 + ar) * K + ak;
    const float* Bld_t = Bb + (size_t)ar * K + ak;
    int bkr = tid >> 4, bn4 = (tid & 15) << 2;
    const float* Bld_n = Bb + (size_t)bkr * N + bn4;

    float acc[4][NT][4];
    #pragma unroll
    for (int mt = 0; mt < 4; mt++)
        #pragma unroll
        for (int nt = 0; nt < NT; nt++)
            #pragma unroll
            for (int c = 0; c < 4; c++) acc[mt][nt][c] = 0.f;

    float4 av[2], bv[2];
    auto ldG = [&](int k0) {
        av[0] = *(const float4*)(Ald + k0);
        av[1] = *(const float4*)(Ald + (size_t)64 * K + k0);
        if (BTRANS) {
            bv[0] = *(const float4*)(Bld_t + k0);
            if (TN == 128) bv[1] = *(const float4*)(Bld_t + (size_t)64 * K + k0);
        } else {
            bv[0] = *(const float4*)(Bld_n + (size_t)k0 * N);
        }
    };
    auto stS = [&](int buf) {
        #pragma unroll
        for (int h = 0; h < 2; h++) {
            int r = ar + h * 64;
            As[buf][ak+0][r] = to_tf32(((const float*)&av[h])[0]);
            As[buf][ak+1][r] = to_tf32(((const float*)&av[h])[1]);
            As[buf][ak+2][r] = to_tf32(((const float*)&av[h])[2]);
            As[buf][ak+3][r] = to_tf32(((const float*)&av[h])[3]);
        }
        if (BTRANS) {
            #pragma unroll
            for (int h = 0; h < (TN == 128 ? 2 : 1); h++) {
                int r = ar + h * 64;
                if (TN == 128 || r < TN) {
                    Bs[buf][ak+0][r] = to_tf32(((const float*)&bv[h])[0]);
                    Bs[buf][ak+1][r] = to_tf32(((const float*)&bv[h])[1]);
                    Bs[buf][ak+2][r] = to_tf32(((const float*)&bv[h])[2]);
                    Bs[buf][ak+3][r] = to_tf32(((const float*)&bv[h])[3]);
                }
            }
        } else {
            float4 t = make_float4(to_tf32(bv[0].x), to_tf32(bv[0].y),
                                   to_tf32(bv[0].z), to_tf32(bv[0].w));
            *(float4*)&Bs[buf][bkr][bn4] = t;
        }
    };
    auto compute = [&](int buf) {
        #pragma unroll
        for (int ks = 0; ks < 2; ks++) {
            int kb = ks * 8;
            uint32_t af[4][4], bf[NT][2];
            #pragma unroll
            for (int mt = 0; mt < 4; mt++) {
                int mb = wm * 64 + mt * 16;
                af[mt][0] = __float_as_uint(As[buf][kb+qc  ][mb+qr  ]);
                af[mt][1] = __float_as_uint(As[buf][kb+qc  ][mb+qr+8]);
                af[mt][2] = __float_as_uint(As[buf][kb+qc+4][mb+qr  ]);
                af[mt][3] = __float_as_uint(As[buf][kb+qc+4][mb+qr+8]);
            }
            #pragma unroll
            for (int nt = 0; nt < NT; nt++) {
                int nb = wn * WN + nt * 8;
                bf[nt][0] = __float_as_uint(Bs[buf][kb+qc  ][nb+qr]);
                bf[nt][1] = __float_as_uint(Bs[buf][kb+qc+4][nb+qr]);
            }
            #pragma unroll
            for (int mt = 0; mt < 4; mt++)
                #pragma unroll
                for (int nt = 0; nt < NT; nt++)
                    mma_tf32(acc[mt][nt], af[mt], bf[nt]);
        }
    };

    ldG(0);
    stS(0);
    __syncthreads();
    int buf = 0;
    for (int k0 = 16; k0 < K; k0 += 16) {
        ldG(k0);
        compute(buf);
        stS(buf ^ 1);
        __syncthreads();
        buf ^= 1;
    }
    compute(buf);

    #pragma unroll
    for (int mt = 0; mt < 4; mt++) {
        int rbase = row0 + wm * 64 + mt * 16 + qr;
        #pragma unroll
        for (int nt = 0; nt < NT; nt++) {
            int cg = col0 + wn * WN + nt * 8 + 2 * qc;
            #pragma unroll
            for (int hh = 0; hh < 2; hh++) {
                int r = rbase + hh * 8;
                float2 v = make_float2(acc[mt][nt][2*hh], acc[mt][nt][2*hh+1]);
                if (BIAS) { v.x += bias[cg]; v.y += bias[cg+1]; }
                if (RESID) {
                    const float2 rz = *(const float2*)(resid + (size_t)r * N + cg);
                    v.x += rz.x; v.y += rz.y;
                }
                if (RELU) { v.x = fmaxf(v.x, 0.f); v.y = fmaxf(v.y, 0.f); }
                if (MAP == 0) {
                    *(float2*)(C + (size_t)r * N + cg) = v;
                } else {
                    int b = z >> 3, h2 = z & 7;
                    *(float2*)(g_heads + ((size_t)(b * NSEQ) + r) * DMODEL + h2 * DK + cg) = v;
                }
            }
        }
    }
}

// ============================================================================
// scores prep: convert K and the 5 Q' channels to bf16 hi/lo fragment planes.
// ============================================================================
__global__ __launch_bounds__(256)
void scores_prep_kernel()
{
    __shared__ float sw[320];
    int tid = threadIdx.x;
    int g = blockIdx.x, z = blockIdx.y;
    if (tid < DK) {
        #pragma unroll
        for (int p = 0; p < 4; p++) sw[p*64 + tid] = g_Mmat[tid*4+p];
        sw[256 + tid] = g_cvec[tid];
    }
    __syncthreads();

    {
        int jl = tid >> 2, tq = tid & 3;
        const float* kp = g_k + ((size_t)z*NSEQ + g*64 + jl)*DK;
        uint32_t* dst = reinterpret_cast<uint32_t*>(g_kfrag) + (size_t)(z*8 + g)*4096;
        int qrj = jl & 7, jhalf = (jl >> 3) & 1, mg = jl >> 4;
        #pragma unroll
        for (int u = 0; u < 8; u++) {
            int d0 = 2*(tq + u*4);
            float2 kv = *(const float2*)(kp + d0);
            float h0 = bfhi(kv.x), h1 = bfhi(kv.y);
            int ks = d0 >> 4, kk = d0 & 15, qcc = (kk >> 1) & 3, khalf = kk >> 3;
            int base = ((mg*4 + ks)*32 + qrj*4 + qcc)*4 + (jhalf + 2*khalf);
            dst[base]        = pkbf2(h0, h1);
            dst[2048 + base] = pkbf2(kv.x - h0, kv.y - h1);
        }
    }

    {
        int il = tid >> 2, tq = tid & 3;
        int ig = g*2 + (il >> 5), iin = il & 31;
        const float* qp = g_q + ((size_t)z*NSEQ + g*64 + il)*DK;
        int qri = iin & 7, ng = iin >> 3;
        uint32_t* bd0 = reinterpret_cast<uint32_t*>(g_qfrag)
                      + (size_t)(z*16 + ig)*5*2048;
        #pragma unroll
        for (int u = 0; u < 8; u++) {
            int d0 = 2*(tq + u*4);
            float2 qv = *(const float2*)(qp + d0);
            int ks = d0 >> 4, kk = d0 & 15, qcc = (kk >> 1) & 3, khalf = kk >> 3;
            int fb = ((ng*4 + ks)*32 + qri*4 + qcc)*4;
            #pragma unroll
            for (int ch = 0; ch < 5; ch++) {
                float p0 = qv.x * sw[ch*64 + d0];
                float p1 = qv.y * sw[ch*64 + d0 + 1];
                float h0 = bfhi(p0), h1 = bfhi(p1);
                uint32_t* bd = bd0 + ch*2048;
                bd[fb + khalf]     = pkbf2(h0, h1);
                bd[fb + 2 + khalf] = pkbf2(p0 - h0, p1 - h1);
            }
        }
    }
}

// ============================================================================
// scores v6: all 8 heads per block (pos loaded ONCE into registers).
// Block = 64j x 32i of one batch; 8 warps; bf16 3-term m16n8k16.
// ============================================================================
__global__ __launch_bounds__(256)
void scores_tc_kernel(const float* __restrict__ pos, float* __restrict__ attn)
{
    int tid  = threadIdx.x;
    int lane = tid & 31, warp = tid >> 5;
    int wm = warp >> 2, wn = warp & 3;
    int qr = lane >> 2, qc = lane & 3;
    int ig = blockIdx.x, jg = blockIdx.y, bbx = blockIdx.z;
    int i0 = ig << 5, j0 = jg << 6;
    int colb = i0 + wn*8 + 2*qc;

    // preload pos for this thread's 4 output points (shared by all 8 heads)
    float4 pr[2][2][2];
    #pragma unroll
    for (int mt = 0; mt < 2; mt++)
        #pragma unroll
        for (int hf = 0; hf < 2; hf++) {
            int row = j0 + wm*32 + mt*16 + qr + 8*hf;
            const float* pp = pos + (((size_t)(bbx*NSEQ + row))*NSEQ + colb)*4;
            pr[mt][hf][0] = *(const float4*)pp;
            pr[mt][hf][1] = *(const float4*)(pp + 4);
        }

    #pragma unroll 1
    for (int h = 0; h < NH; h++) {
        int z = bbx*NH + h;
        const uint4* Af = g_kfrag + (size_t)(z*8 + jg)*1024;
        const uint4* Bf = g_qfrag + (size_t)(z*16 + ig)*2560 + wn*128 + lane;

        float acc[5][2][4];
        #pragma unroll
        for (int ch = 0; ch < 5; ch++)
            #pragma unroll
            for (int mt = 0; mt < 2; mt++)
                #pragma unroll
                for (int c = 0; c < 4; c++) acc[ch][mt][c] = 0.f;

        #pragma unroll
        for (int ks = 0; ks < 4; ks++) {
            uint4 ah[2], al[2];
            #pragma unroll
            for (int mt = 0; mt < 2; mt++) {
                int fi = (wm*2 + mt)*128 + ks*32 + lane;
                ah[mt] = __ldg(&Af[fi]);
                al[mt] = __ldg(&Af[512 + fi]);
            }
            #pragma unroll
            for (int ch = 0; ch < 5; ch++) {
                uint4 bq = __ldg(&Bf[ch*512 + ks*32]);
                #pragma unroll
                for (int mt = 0; mt < 2; mt++) {
                    mma_bf16(acc[ch][mt], ah[mt], bq.x, bq.y);
                    mma_bf16(acc[ch][mt], ah[mt], bq.z, bq.w);
                    mma_bf16(acc[ch][mt], al[mt], bq.x, bq.y);
                }
            }
        }

        #pragma unroll
        for (int mt = 0; mt < 2; mt++)
            #pragma unroll
            for (int hf = 0; hf < 2; hf++) {
                int row = j0 + wm*32 + mt*16 + qr + 8*hf;
                float4 p0 = pr[mt][hf][0];
                float4 p1 = pr[mt][hf][1];
                int c = 2*hf;
                float s0 = acc[4][mt][c]
                         + p0.x*acc[0][mt][c] + p0.y*acc[1][mt][c]
                         + p0.z*acc[2][mt][c] + p0.w*acc[3][mt][c];
                float s1 = acc[4][mt][c+1]
                         + p1.x*acc[0][mt][c+1] + p1.y*acc[1][mt][c+1]
                         + p1.z*acc[2][mt][c+1] + p1.w*acc[3][mt][c+1];
                *(float2*)(attn + ((size_t)z*NSEQ + row)*NSEQ + colb) =
                    make_float2(s0*INV_T, s1*INV_T);
            }
    }
}

// ---------------- softmax: warp per row, 8 rows per block, float4 -----------
__global__ __launch_bounds__(256)
void softmax_kernel(float* __restrict__ attn)
{
    int warp = threadIdx.x >> 5, lane = threadIdx.x & 31;
    size_t row = (size_t)blockIdx.x * 8 + warp;
    float4* p = reinterpret_cast<float4*>(attn + row * NSEQ);

    float4 v[4];
    #pragma unroll
    for (int u = 0; u < 4; u++) v[u] = p[lane + 32*u];

    float m = -1e30f;
    #pragma unroll
    for (int u = 0; u < 4; u++)
        m = fmaxf(m, fmaxf(fmaxf(v[u].x, v[u].y), fmaxf(v[u].z, v[u].w)));
    m = warp_max(m);

    float s = 0.f;
    #pragma unroll
    for (int u = 0; u < 4; u++) {
        v[u].x = __expf(v[u].x - m); v[u].y = __expf(v[u].y - m);
        v[u].z = __expf(v[u].z - m); v[u].w = __expf(v[u].w - m);
        s += v[u].x + v[u].y + v[u].z + v[u].w;
    }
    s = warp_sum(s);
    float inv = 1.0f / s;
    #pragma unroll
    for (int u = 0; u < 4; u++) {
        v[u].x *= inv; v[u].y *= inv; v[u].z *= inv; v[u].w *= inv;
        p[lane + 32*u] = v[u];
    }
}

// ---------------- layer norm (one token per block) ---------------------------
__global__ __launch_bounds__(256)
void layernorm_kernel(const float* __restrict__ x, const float* __restrict__ gam,
                      const float* __restrict__ bet, float* __restrict__ out)
{
    int t = blockIdx.x, tid = threadIdx.x;
    const float* xr = x + (size_t)t * DMODEL;
    __shared__ float red[8];

    float a0 = xr[tid], a1 = xr[tid + 256];
    float s = warp_sum(a0 + a1);
    if ((tid & 31) == 0) red[tid >> 5] = s;
    __syncthreads();
    s = red[0];
    #pragma unroll
    for (int w = 1; w < 8; w++) s += red[w];
    float mu = s * (1.0f / DMODEL);
    float d0 = a0 - mu, d1 = a1 - mu;
    __syncthreads();

    float q = warp_sum(d0*d0 + d1*d1);
    if ((tid & 31) == 0) red[tid >> 5] = q;
    __syncthreads();
    q = red[0];
    #pragma unroll
    for (int w = 1; w < 8; w++) q += red[w];
    float inv = rsqrtf(q * (1.0f / DMODEL) + LN_EPS);

    float* orow = out + (size_t)t * DMODEL;
    orow[tid]       = d0 * inv * gam[tid]       + bet[tid];
    orow[tid + 256] = d1 * inv * gam[tid + 256] + bet[tid + 256];
}

// ---------------- launch -----------------------------------------------------
extern "C" void kernel_launch(void* const* d_in, const int* in_sizes, int n_in,
                              void* d_out, int out_size)
{
    (void)in_sizes; (void)n_in; (void)out_size;
    const float* enc    = (const float*)d_in[0];
    const float* pos    = (const float*)d_in[1];
    const float* w_qs   = (const float*)d_in[2];
    const float* w_ks   = (const float*)d_in[3];
    const float* w_vs   = (const float*)d_in[4];
    const float* w_fc   = (const float*)d_in[5];
    const float* rp_w1  = (const float*)d_in[6];
    const float* rp_b1  = (const float*)d_in[7];
    const float* rp_w2  = (const float*)d_in[8];
    const float* rp_b2  = (const float*)d_in[9];
    const float* ln1_g  = (const float*)d_in[10];
    const float* ln1_b  = (const float*)d_in[11];
    const float* ln2_g  = (const float*)d_in[12];
    const float* ln2_b  = (const float*)d_in[13];
    const float* ffn_w1 = (const float*)d_in[14];
    const float* ffn_b1 = (const float*)d_in[15];
    const float* ffn_w2 = (const float*)d_in[16];
    const float* ffn_b2 = (const float*)d_in[17];

    float* out2 = (float*)d_out;                          // [4,512,512]
    float* attn = out2 + (size_t)TOK * DMODEL;            // [4,8,512,512]

    float *pv, *pheads, *ptmp1, *pln1, *pffh, *ptmp2;
    cudaGetSymbolAddress((void**)&pv,     g_v);
    cudaGetSymbolAddress((void**)&pheads, g_heads);
    cudaGetSymbolAddress((void**)&ptmp1,  g_tmp1);
    cudaGetSymbolAddress((void**)&pln1,   g_ln1);
    cudaGetSymbolAddress((void**)&pffh,   g_ffh);
    cudaGetSymbolAddress((void**)&ptmp2,  g_tmp2);

    // 1) collapse rel-pos MLP
    rp_combine_kernel<<<1, 64>>>(rp_w1, rp_b1, rp_w2, rp_b2);

    // 2+3) QKV projection, 3-term bf16, two column halves
    {
        dim3 g(6, TOK/128, 1);
        qkv3_kernel<<<g, 256>>>(enc, w_qs, w_ks, w_vs, 0);
        qkv3_kernel<<<g, 256>>>(enc, w_qs, w_ks, w_vs, 768);
    }

    // 4) one-time bf16 fragment conversion (K hi/lo + 5 Q' channels)
    {
        dim3 g(8, BB*NH);                  // 256 blocks
        scores_prep_kernel<<<g, 256>>>();
    }

    // 5) relative-position attention logits (all heads per block)
    {
        dim3 g(NSEQ/32, NSEQ/64, BB);      // (16, 8, 4) = 512 blocks
        scores_tc_kernel<<<g, 256>>>(pos, attn);
    }

    // 6) softmax in place (warp per row)
    softmax_kernel<<<BB*NH*NSEQ/8, 256>>>(attn);

    // 7) AV (tf32): per (b,h): P[512,512] @ V[512,64] -> g_heads
    {
        dim3 g(1, NSEQ/128, BB*NH);
        tgemm_kernel<64, 2, false, false, false, false><<<g, 256>>>(
            attn, pv, nullptr, nullptr, nullptr,
            DK, NSEQ, (size_t)NSEQ*NSEQ, (size_t)NSEQ*DK);
    }

    // 8) fc + residual(enc) -> g_tmp1 (tf32); LN1
    {
        dim3 g(DMODEL/64, TOK/128, 1);
        tgemm_kernel<64, 0, true, false, false, true><<<g, 256>>>(
            pheads, w_fc, nullptr, enc, ptmp1, DMODEL, DMODEL, 0, 0);
    }
    layernorm_kernel<<<TOK, 256>>>(ptmp1, ln1_g, ln1_b, pln1);

    // 9) FFN1 (tf32): relu(ln1 @ W1^T + b1) -> g_ffh
    {
        dim3 g(DINNER/128, TOK/128, 1);
        tgemm_kernel<128, 0, true, true, true, false><<<g, 256>>>(
            pln1, ffn_w1, ffn_b1, nullptr, pffh, DINNER, DMODEL, 0, 0);
    }

    // 10) FFN2 (tf32): ffh @ W2^T + b2 + ln1 -> g_tmp2
    {
        dim3 g(DMODEL/64, TOK/128, 1);
        tgemm_kernel<64, 0, true, true, false, true><<<g, 256>>>(
            pffh, ffn_w2, ffn_b2, pln1, ptmp2, DMODEL, DINNER, 0, 0);
    }

    // 11) LN2 -> out2
    layernorm_kernel<<<TOK, 256>>>(ptmp2, ln2_g, ln2_b, out2);
}